// round 8
// baseline (speedup 1.0000x reference)
#include <cuda_runtime.h>
#include <cstdint>

#define B_   8
#define CIN  64
#define COUT 8
#define H1   128
#define W1   128
#define H2   256
#define W2   256
#define PLANE (H2*W2)   /* 65536 */
#define NUM_ 8
#define NSEG 16

// ---------------- scratch (device globals; no allocation allowed) ----------
__device__ float g_up [(size_t)B_*CIN *PLANE];  // bilinear-upsampled input
__device__ float g_c1 [(size_t)B_*CIN *PLANE];  // conv1+BN+ReLU
__device__ float g_xf [(size_t)B_*COUT*PLANE];  // conv2+BN, thresholded
__device__ float g_rs [(size_t)B_*COUT*PLANE];  // row sums
__device__ unsigned long long g_seg[B_*COUT*NSEG*8]; // per-segment top-8 keys

// ---------------- packed f32x2 helpers --------------------------------------
__device__ __forceinline__ unsigned long long pk2(float lo, float hi) {
    unsigned long long r;
    asm("mov.b64 %0, {%1, %2};" : "=l"(r) : "f"(lo), "f"(hi));
    return r;
}
__device__ __forceinline__ void upk2(unsigned long long v, float& lo, float& hi) {
    asm("mov.b64 {%0, %1}, %2;" : "=f"(lo), "=f"(hi) : "l"(v));
}
#define FMA2(d, a, b) asm("fma.rn.f32x2 %0, %1, %2, %0;" : "+l"(d) : "l"(a), "l"(b))

// ---------------- 1) bilinear 2x upsample (2 outputs/thread) ----------------
// formula identical to the validated round-1 kernel.
__global__ void k_upsample(const float* __restrict__ x) {
    int gid = blockIdx.x * 256 + threadIdx.x;
    int plane = gid >> 15;
    int r2 = gid & 32767;
    int oy = r2 >> 7;
    int kx = r2 & 127;                  // outputs ox = 2kx, 2kx+1
    int y0 = (oy - 1) >> 1;
    float wy = (oy & 1) ? 0.25f : 0.75f;
    int y0c = max(y0, 0), y1c = min(y0 + 1, H1 - 1);
    int cm = max(kx - 1, 0), cp = min(kx + 1, W1 - 1);
    const float* xp = x + ((size_t)plane << 14);
    float r0m = xp[y0c * W1 + cm], r0c = xp[y0c * W1 + kx], r0p = xp[y0c * W1 + cp];
    float r1m = xp[y1c * W1 + cm], r1c = xp[y1c * W1 + kx], r1p = xp[y1c * W1 + cp];
    // even ox = 2kx: x0 = kx-1 (clamped cm), x1 = kx, wx = 0.75
    float te = r0m + 0.75f * (r0c - r0m);
    float be = r1m + 0.75f * (r1c - r1m);
    // odd ox = 2kx+1: x0 = kx, x1 = kx+1 (clamped cp), wx = 0.25
    float to = r0c + 0.25f * (r0p - r0c);
    float bo = r1c + 0.25f * (r1p - r1c);
    float2 o;
    o.x = te + wy * (be - te);
    o.y = to + wy * (bo - to);
    *(float2*)(g_up + ((size_t)plane << 16) + (oy << 8) + 2 * kx) = o;
}

// ============================================================================
// conv1: conv3x3(64->64) over g_up + bias + BN + ReLU
// grid (2, 64, B*4): tile 128(w) x 4(h), co quarter (16) per block.
// fill = one predicated LDG.128 / thread / ci (aligned window x0t-4 .. x0t+131)
// ============================================================================
__global__ __launch_bounds__(256, 3) void k_conv1(
    const float* __restrict__ w1, const float* __restrict__ b1,
    const float* __restrict__ gamma1, const float* __restrict__ beta1,
    const float* __restrict__ mean1, const float* __restrict__ var1)
{
    __shared__ unsigned long long s_w[CIN][9][8];  // [ci][tap][co-pair]
    __shared__ float s_in[2][6][136];              // col c <-> up col x0t-4+c
    __shared__ float s_scale[16], s_shift[16];

    const int tid = threadIdx.x;
    const int xg = tid & 31;
    const int yg = (tid >> 5) & 3;
    const int cg = tid >> 7;
    const int bz  = blockIdx.z;
    const int b   = bz >> 2;
    const int co0 = (bz & 3) * 16;
    const int x0t = blockIdx.x * 128;
    const int y0t = blockIdx.y * 4;

    for (int i = tid; i < CIN * 9 * 8; i += 256) {
        int cp = i & 7; int rest = i >> 3;
        int p = rest % 9; int ci = rest / 9;
        int coA = co0 + 2 * cp;
        float wa = w1[((size_t)coA       * CIN + ci) * 9 + p];
        float wb = w1[((size_t)(coA + 1) * CIN + ci) * 9 + p];
        s_w[ci][p][cp] = pk2(wa, wb);
    }
    if (tid < 16) {
        int co = co0 + tid;
        float a = gamma1[co] * rsqrtf(var1[co] + 1e-5f);
        s_scale[tid] = a;
        s_shift[tid] = fmaf(a, b1[co] - mean1[co], beta1[co]);
    }

    // fill geometry: 204 float4 slots (6 rows x 34)
    const bool act = tid < 204;
    const int fr  = tid / 34;
    const int fc4 = tid - fr * 34;
    const int fgy = y0t + fr - 1;
    const bool rowok = act && (fgy >= 0) && (fgy < H2);
    const int fgx = x0t - 4 + 4 * fc4;
    const bool full = rowok && (fgx >= 0) && (fgx <= W2 - 4);
    const float* uprow = g_up + ((size_t)b * CIN << 16) + ((size_t)(rowok ? fgy : 0) << 8);

#define LOADV(ci, v) do {                                                     \
        (v) = make_float4(0.f, 0.f, 0.f, 0.f);                                \
        const float* up_ = uprow + ((size_t)(ci) << 16);                      \
        if (full) (v) = *(const float4*)(up_ + fgx);                          \
        else if (rowok) {                                                     \
            _Pragma("unroll")                                                 \
            for (int j_ = 0; j_ < 4; j_++) {                                  \
                int c_ = fgx + j_;                                            \
                if (c_ >= 0 && c_ < W2) ((float*)&(v))[j_] = up_[c_];         \
            }                                                                 \
        }                                                                     \
    } while (0)

    {
        float4 v0;
        LOADV(0, v0);
        if (act) *(float4*)&s_in[0][fr][4 * fc4] = v0;
    }
    __syncthreads();

    unsigned long long acc[4][4];
#pragma unroll
    for (int q = 0; q < 4; q++)
#pragma unroll
        for (int j = 0; j < 4; j++) acc[q][j] = 0ull;

    for (int ci = 0; ci < CIN; ci++) {
        const int cur = ci & 1;

        float4 lv;
        if (ci < CIN - 1) LOADV(ci + 1, lv);

#pragma unroll
        for (int kr = 0; kr < 3; kr++) {
            const float* row = &s_in[cur][yg + kr][4 * xg];
            float4 A  = *(const float4*)row;        // cols 4xg .. +3 (use .w)
            float4 Bv = *(const float4*)(row + 4);  // cols +4 .. +7
            float  C  = row[8];                     // col  +8
            unsigned long long Q[6];
            Q[0] = pk2(A.w,  A.w);
            Q[1] = pk2(Bv.x, Bv.x);
            Q[2] = pk2(Bv.y, Bv.y);
            Q[3] = pk2(Bv.z, Bv.z);
            Q[4] = pk2(Bv.w, Bv.w);
            Q[5] = pk2(C,    C);
#pragma unroll
            for (int kc = 0; kc < 3; kc++) {
                const ulonglong2* wrow =
                    (const ulonglong2*)&s_w[ci][kr * 3 + kc][cg * 4];
                ulonglong2 wA = wrow[0];
                ulonglong2 wB = wrow[1];
#pragma unroll
                for (int q = 0; q < 4; q++) {
                    unsigned long long iv = Q[kc + q];
                    FMA2(acc[q][0], iv, wA.x);
                    FMA2(acc[q][1], iv, wA.y);
                    FMA2(acc[q][2], iv, wB.x);
                    FMA2(acc[q][3], iv, wB.y);
                }
            }
        }

        if (act && ci < CIN - 1) *(float4*)&s_in[cur ^ 1][fr][4 * fc4] = lv;
        __syncthreads();
    }
#undef LOADV

    const int oy = y0t + yg;
    const int ox = x0t + 4 * xg;
    float* outb = g_c1 + (((size_t)b * CIN + co0 + 8 * cg) << 16) + (oy << 8) + ox;
#pragma unroll
    for (int j = 0; j < 4; j++) {
        float va[4], vb[4];
#pragma unroll
        for (int q = 0; q < 4; q++) upk2(acc[q][j], va[q], vb[q]);
        const int cr = 8 * cg + 2 * j;
        const float sa = s_scale[cr],     sha = s_shift[cr];
        const float sb = s_scale[cr + 1], shb = s_shift[cr + 1];
        float4 oa, ob;
        oa.x = fmaxf(fmaf(sa, va[0], sha), 0.f);
        oa.y = fmaxf(fmaf(sa, va[1], sha), 0.f);
        oa.z = fmaxf(fmaf(sa, va[2], sha), 0.f);
        oa.w = fmaxf(fmaf(sa, va[3], sha), 0.f);
        ob.x = fmaxf(fmaf(sb, vb[0], shb), 0.f);
        ob.y = fmaxf(fmaf(sb, vb[1], shb), 0.f);
        ob.z = fmaxf(fmaf(sb, vb[2], shb), 0.f);
        ob.w = fmaxf(fmaf(sb, vb[3], shb), 0.f);
        *(float4*)(outb + ((size_t)(2 * j)     << 16)) = oa;
        *(float4*)(outb + ((size_t)(2 * j + 1) << 16)) = ob;
    }
}

// ---------------- conv1x1(64->8) + BN + threshold + fused row-sum -----------
__global__ __launch_bounds__(256) void k_conv2rs(
    const float* __restrict__ w2,
    const float* __restrict__ gamma2, const float* __restrict__ beta2,
    const float* __restrict__ mean2, const float* __restrict__ var2)
{
    __shared__ unsigned long long s_wp[8][64];
    __shared__ float s_scale[8], s_shift[8];
    __shared__ float s_xf[8][4][264];   // data at idx 4..259; halo 2,3,260,261
    const int tid = threadIdx.x;
    const int b  = blockIdx.x >> 6;
    const int y0 = (blockIdx.x & 63) * 4;
    const int r = tid >> 6;
    const int col0 = (tid & 63) * 4;

    if (tid < 8) {
        float a = gamma2[tid] * rsqrtf(var2[tid] + 1e-5f);
        s_scale[tid] = a;
        s_shift[tid] = beta2[tid] - a * mean2[tid];
    }
    for (int i = tid; i < 512; i += 256) {
        int co = i >> 6, ci = i & 63;
        float w = w2[co * 64 + ci];
        s_wp[co][ci] = pk2(w, w);
    }
    if (tid < 128) {
        int co = tid >> 4, rr = (tid >> 2) & 3, which = tid & 3;
        const int idxs[4] = {2, 3, 260, 261};
        s_xf[co][rr][idxs[which]] = 0.f;
    }
    __syncthreads();

    const ulonglong2* c1 = (const ulonglong2*)
        (g_c1 + ((size_t)b * CIN << 16) + ((size_t)(y0 + r) << 8) + col0);
    unsigned long long a01[8], a23[8];
#pragma unroll
    for (int co = 0; co < 8; co++) { a01[co] = 0ull; a23[co] = 0ull; }
#pragma unroll 8
    for (int ci = 0; ci < CIN; ci++) {
        ulonglong2 v = c1[(size_t)ci * 16384];
#pragma unroll
        for (int co = 0; co < 8; co++) {
            unsigned long long w = s_wp[co][ci];
            FMA2(a01[co], v.x, w);
            FMA2(a23[co], v.y, w);
        }
    }

    const size_t rowoff = ((size_t)(y0 + r) << 8) + col0;
#pragma unroll
    for (int co = 0; co < 8; co++) {
        float f0, f1, f2, f3;
        upk2(a01[co], f0, f1);
        upk2(a23[co], f2, f3);
        const float sc = s_scale[co], sh = s_shift[co];
        float o0 = fmaf(sc, f0, sh), o1 = fmaf(sc, f1, sh);
        float o2 = fmaf(sc, f2, sh), o3 = fmaf(sc, f3, sh);
        float4 xf;
        xf.x = (o0 > 1.0f) ? o0 : 0.f;
        xf.y = (o1 > 1.0f) ? o1 : 0.f;
        xf.z = (o2 > 1.0f) ? o2 : 0.f;
        xf.w = (o3 > 1.0f) ? o3 : 0.f;
        *(float4*)(g_xf + (((size_t)b * COUT + co) << 16) + rowoff) = xf;
        *(float4*)&s_xf[co][r][col0 + 4] = xf;
    }
    __syncthreads();

#pragma unroll
    for (int co = 0; co < 8; co++) {
        const float* f = &s_xf[co][r][col0 + 2];
        float4 s;
        s.x = f[0] + f[1] + f[2] + f[3] + f[4];
        s.y = f[1] + f[2] + f[3] + f[4] + f[5];
        s.z = f[2] + f[3] + f[4] + f[5] + f[6];
        s.w = f[3] + f[4] + f[5] + f[6] + f[7];
        *(float4*)(g_rs + (((size_t)b * COUT + co) << 16) + rowoff) = s;
    }
}

// ---------------- fused ws + rowmax + NMS + per-segment top-8 ---------------
// block = (plane, 16-row segment). ws/rm live only in smem.
__global__ __launch_bounds__(256) void k_nms() {
    __shared__ __align__(16) float s_rs[24][256];   // aliased by s_rm after use
    __shared__ __align__(16) float s_ws[20][260];   // data cols 2..257; halo -1
    float (*s_rm)[256] = (float (*)[256])&s_rs[0][0];
    unsigned long long* s_keys = (unsigned long long*)&s_ws[0][0];

    const int bid = blockIdx.x;
    const int pl = bid >> 4;
    const int seg = bid & 15;
    const int y0 = seg * 16;
    const int x = threadIdx.x;
    const float* rs = g_rs + ((size_t)pl << 16);

#pragma unroll
    for (int i = 0; i < 24; i++) {
        int row = y0 - 4 + i;
        s_rs[i][x] = (row >= 0 && row < 256) ? rs[(row << 8) + x] : 0.f;
    }
    if (x < 80) {
        int rr = x >> 2, which = x & 3;
        const int idxs[4] = {0, 1, 258, 259};
        s_ws[rr][idxs[which]] = -1.f;
    }
    __syncthreads();

    // ws rows y0-2 .. y0+17 (OOB rows = -1, matching -inf pad semantics)
#pragma unroll
    for (int i = 0; i < 20; i++) {
        int y = y0 - 2 + i;
        float w;
        if (y >= 0 && y < 256)
            w = s_rs[i][x] + s_rs[i + 1][x] + s_rs[i + 2][x]
              + s_rs[i + 3][x] + s_rs[i + 4][x];
        else
            w = -1.f;
        s_ws[i][x + 2] = w;
    }
    __syncthreads();   // s_rs reads done -> s_rm may overwrite

#pragma unroll
    for (int i = 0; i < 20; i++) {
        const float* wr = &s_ws[i][x];
        s_rm[i][x] = fmaxf(fmaxf(fmaxf(wr[0], wr[1]), fmaxf(wr[2], wr[3])), wr[4]);
    }
    __syncthreads();

    unsigned long long k[8];
#pragma unroll
    for (int j = 0; j < 8; j++) k[j] = 0ull;

#pragma unroll
    for (int i = 0; i < 16; i++) {
        float m = fmaxf(fmaxf(fmaxf(s_rm[i][x], s_rm[i + 1][x]),
                              fmaxf(s_rm[i + 2][x], s_rm[i + 3][x])),
                        s_rm[i + 4][x]);
        float v = s_ws[i + 2][x + 2];
        if (v == m) {
            unsigned pos = (unsigned)(((y0 + i) << 8) + x);
            unsigned long long key =
                ((unsigned long long)__float_as_uint(v) << 32) | (unsigned)(~pos);
            if (key > k[7]) {
                int p = 7;
#pragma unroll
                for (int q = 7; q > 0; q--) {
                    if (key > k[q - 1]) { k[q] = k[q - 1]; p = q - 1; }
                }
                k[p] = key;
            }
        }
    }
    __syncthreads();   // s_ws reads done -> s_keys may overwrite

#pragma unroll
    for (int j = 0; j < 8; j++) s_keys[x * 8 + j] = k[j];
    __syncthreads();

    for (int off = 128; off > 0; off >>= 1) {
        if (x < off) {
            unsigned long long* a = &s_keys[x * 8];
            unsigned long long* b = &s_keys[(x + off) * 8];
            unsigned long long out[8];
            int i = 0, j = 0;
#pragma unroll
            for (int t = 0; t < 8; t++)
                out[t] = (a[i] >= b[j]) ? a[i++] : b[j++];
#pragma unroll
            for (int t = 0; t < 8; t++) a[t] = out[t];
        }
        __syncthreads();
    }
    if (x < 8) g_seg[bid * 8 + x] = s_keys[x];
}

// ---------------- top-k stage 2 (merge NSEG*8 keys) + fused gather ----------
__global__ __launch_bounds__(128) void k_topk2(float* __restrict__ out) {
    __shared__ unsigned long long s[NSEG * 8];
    __shared__ unsigned long long top[8];
    const int bc = blockIdx.x;
    const int tid = threadIdx.x;

    s[tid] = g_seg[bc * (NSEG * 8) + tid];
    __syncthreads();

    if (tid == 0) {
        unsigned long long k[8];
#pragma unroll
        for (int j = 0; j < 8; j++) k[j] = 0ull;
        for (int i = 0; i < NSEG * 8; i++) {
            unsigned long long key = s[i];
            if (key > k[7]) {
                int p = 7;
#pragma unroll
                for (int q = 7; q > 0; q--) {
                    if (key > k[q - 1]) { k[q] = k[q - 1]; p = q - 1; }
                }
                k[p] = key;
            }
        }
#pragma unroll
        for (int j = 0; j < 8; j++) top[j] = k[j];
    }
    __syncthreads();

    if (tid < 8) {
        unsigned pos = ~(unsigned)(top[tid] & 0xFFFFFFFFull);
        int h = pos >> 8, w = pos & 255;
        const int gid = bc * 8 + tid;
        const float* xf = g_xf + (size_t)bc * PLANE;
        float* po = out + gid * 25;
#pragma unroll
        for (int dy = 0; dy < 5; dy++) {
            int yy = h + dy - 2;
#pragma unroll
            for (int dx = 0; dx < 5; dx++) {
                int xx = w + dx - 2;
                float v = 0.f;
                if (yy >= 0 && yy < 256 && xx >= 0 && xx < 256) v = xf[yy * 256 + xx];
                po[dy * 5 + dx] = v;
            }
        }
        float* pp = out + B_ * COUT * NUM_ * 25 + gid * 4;
        pp[0] = (float)min(max(w - 2, 0), 255);
        pp[1] = (float)min(max(h - 2, 0), 255);
        pp[2] = (float)min(max(w + 2, 0), 255);
        pp[3] = (float)min(max(h + 2, 0), 255);
    }
}

// ---------------- launch ------------------------------------------------------
extern "C" void kernel_launch(void* const* d_in, const int* in_sizes, int n_in,
                              void* d_out, int out_size) {
    const float* x      = (const float*)d_in[0];
    const float* w1     = (const float*)d_in[1];
    const float* b1     = (const float*)d_in[2];
    const float* gamma1 = (const float*)d_in[3];
    const float* beta1  = (const float*)d_in[4];
    const float* mean1  = (const float*)d_in[5];
    const float* var1   = (const float*)d_in[6];
    const float* w2     = (const float*)d_in[7];
    const float* gamma2 = (const float*)d_in[8];
    const float* beta2  = (const float*)d_in[9];
    const float* mean2  = (const float*)d_in[10];
    const float* var2   = (const float*)d_in[11];
    float* out = (float*)d_out;

    k_upsample<<<(B_ * CIN * PLANE / 2) / 256, 256>>>(x);

    dim3 cg(2, 64, B_ * 4);
    k_conv1<<<cg, 256>>>(w1, b1, gamma1, beta1, mean1, var1);

    k_conv2rs<<<B_ * 64, 256>>>(w2, gamma2, beta2, mean2, var2);

    k_nms<<<B_ * COUT * NSEG, 256>>>();
    k_topk2<<<B_ * COUT, NSEG * 8>>>(out);
}

// round 9
// speedup vs baseline: 1.0756x; 1.0756x over previous
#include <cuda_runtime.h>
#include <cstdint>

#define B_   8
#define CIN  64
#define COUT 8
#define H1   128
#define W1   128
#define H2   256
#define W2   256
#define PLANE (H2*W2)   /* 65536 */
#define NUM_ 8
#define NSEG 16

// ---------------- scratch (device globals; no allocation allowed) ----------
__device__ float g_c1 [(size_t)B_*CIN *PLANE];  // conv1+BN+ReLU
__device__ float g_xf [(size_t)B_*COUT*PLANE];  // conv2+BN, thresholded
__device__ float g_rs [(size_t)B_*COUT*PLANE];  // row sums
__device__ unsigned long long g_seg[B_*COUT*NSEG*8]; // per-segment top-8 keys

// ---------------- packed f32x2 helpers --------------------------------------
__device__ __forceinline__ unsigned long long pk2(float lo, float hi) {
    unsigned long long r;
    asm("mov.b64 %0, {%1, %2};" : "=l"(r) : "f"(lo), "f"(hi));
    return r;
}
__device__ __forceinline__ void upk2(unsigned long long v, float& lo, float& hi) {
    asm("mov.b64 {%0, %1}, %2;" : "=f"(lo), "=f"(hi) : "l"(v));
}
#define FMA2(d, a, b) asm("fma.rn.f32x2 %0, %1, %2, %0;" : "+l"(d) : "l"(a), "l"(b))

// ============================================================================
// conv1: fused bilinear-2x-upsample + conv3x3(64->64) + bias + BN + ReLU
// (round-7 configuration — best measured: x stays L2-resident, run-based fill)
// ============================================================================
__global__ __launch_bounds__(256, 3) void k_conv1(
    const float* __restrict__ x,
    const float* __restrict__ w1, const float* __restrict__ b1,
    const float* __restrict__ gamma1, const float* __restrict__ beta1,
    const float* __restrict__ mean1, const float* __restrict__ var1)
{
    __shared__ unsigned long long s_w[CIN][9][8];  // [ci][tap][co-pair]
    __shared__ float s_in[2][6][136];
    __shared__ float s_scale[16], s_shift[16];

    const int tid = threadIdx.x;
    const int xg = tid & 31;
    const int yg = (tid >> 5) & 3;
    const int cg = tid >> 7;
    const int bz  = blockIdx.z;
    const int b   = bz >> 2;
    const int co0 = (bz & 3) * 16;
    const int x0t = blockIdx.x * 128;
    const int y0t = blockIdx.y * 4;

    const float* xb = x + (size_t)b * CIN * (H1 * W1);

    for (int i = tid; i < CIN * 9 * 8; i += 256) {
        int cp = i & 7; int rest = i >> 3;
        int p = rest % 9; int ci = rest / 9;
        int coA = co0 + 2 * cp;
        float wa = w1[((size_t)coA       * CIN + ci) * 9 + p];
        float wb = w1[((size_t)(coA + 1) * CIN + ci) * 9 + p];
        s_w[ci][p][cp] = pk2(wa, wb);
    }
    if (tid < 16) {
        int co = co0 + tid;
        float a = gamma1[co] * rsqrtf(var1[co] + 1e-5f);
        s_scale[tid] = a;
        s_shift[tid] = fmaf(a, b1[co] - mean1[co], beta1[co]);
    }

    const bool runA = tid < 198;
    const int ur  = tid / 33;
    const int c0r = (tid - ur * 33) * 4;
    const int gy  = y0t + ur - 1;
    const int gx0 = x0t + c0r - 1;
    const int sy  = (gy - 1) >> 1;
    const int ro0 = min(max(sy, 0), H1 - 1) * W1;
    const int ro1 = min(max(sy + 1, 0), H1 - 1) * W1;
    const float wyv = (gy & 1) ? 0.25f : 0.75f;
    const int S   = (gx0 - 1) >> 1;
    const int cS0 = min(max(S, 0), W1 - 1);
    const int cS1 = min(max(S + 1, 0), W1 - 1);
    const int cS2 = min(max(S + 2, 0), W1 - 1);
    const bool rowOK = (gy >= 0) && (gy < H2);
    bool mok[4];
#pragma unroll
    for (int j = 0; j < 4; j++) {
        int gx = gx0 + j;
        mok[j] = rowOK && (gx >= 0) && (gx < W2);
    }

#define BILIN(buf, p0a, p0b, p0c, p1a, p1b, p1c) do {                         \
        float t0 = p0a + 0.25f * (p0b - p0a);                                 \
        float t1 = p0a + 0.75f * (p0b - p0a);                                 \
        float t2 = p0b + 0.25f * (p0c - p0b);                                 \
        float t3 = p0b + 0.75f * (p0c - p0b);                                 \
        float u0 = p1a + 0.25f * (p1b - p1a);                                 \
        float u1 = p1a + 0.75f * (p1b - p1a);                                 \
        float u2 = p1b + 0.25f * (p1c - p1b);                                 \
        float u3 = p1b + 0.75f * (p1c - p1b);                                 \
        float4 o;                                                             \
        o.x = mok[0] ? (t0 + wyv * (u0 - t0)) : 0.f;                          \
        o.y = mok[1] ? (t1 + wyv * (u1 - t1)) : 0.f;                          \
        o.z = mok[2] ? (t2 + wyv * (u2 - t2)) : 0.f;                          \
        o.w = mok[3] ? (t3 + wyv * (u3 - t3)) : 0.f;                          \
        *(float4*)&s_in[buf][ur][c0r] = o;                                    \
    } while (0)

    if (runA) {
        const float* xp = xb;
        float a0 = xp[ro0 + cS0], a1 = xp[ro0 + cS1], a2 = xp[ro0 + cS2];
        float b0 = xp[ro1 + cS0], b1v = xp[ro1 + cS1], b2 = xp[ro1 + cS2];
        BILIN(0, a0, a1, a2, b0, b1v, b2);
    }
    __syncthreads();

    unsigned long long acc[4][4];
#pragma unroll
    for (int q = 0; q < 4; q++)
#pragma unroll
        for (int j = 0; j < 4; j++) acc[q][j] = 0ull;

    for (int ci = 0; ci < CIN; ci++) {
        const int cur = ci & 1;

        float p0a, p0b, p0c, p1a, p1b, p1c;
        if (runA && ci < CIN - 1) {
            const float* xp = xb + ((size_t)(ci + 1) << 14);
            p0a = xp[ro0 + cS0]; p0b = xp[ro0 + cS1]; p0c = xp[ro0 + cS2];
            p1a = xp[ro1 + cS0]; p1b = xp[ro1 + cS1]; p1c = xp[ro1 + cS2];
        }

#pragma unroll
        for (int kr = 0; kr < 3; kr++) {
            const float* row = &s_in[cur][yg + kr][4 * xg];
            float4 F = *(const float4*)row;
            float2 G = *(const float2*)(row + 4);
            unsigned long long Q[6];
            Q[0] = pk2(F.x, F.x);
            Q[1] = pk2(F.y, F.y);
            Q[2] = pk2(F.z, F.z);
            Q[3] = pk2(F.w, F.w);
            Q[4] = pk2(G.x, G.x);
            Q[5] = pk2(G.y, G.y);
#pragma unroll
            for (int kc = 0; kc < 3; kc++) {
                const ulonglong2* wrow =
                    (const ulonglong2*)&s_w[ci][kr * 3 + kc][cg * 4];
                ulonglong2 wA = wrow[0];
                ulonglong2 wB = wrow[1];
#pragma unroll
                for (int q = 0; q < 4; q++) {
                    unsigned long long iv = Q[kc + q];
                    FMA2(acc[q][0], iv, wA.x);
                    FMA2(acc[q][1], iv, wA.y);
                    FMA2(acc[q][2], iv, wB.x);
                    FMA2(acc[q][3], iv, wB.y);
                }
            }
        }

        if (runA && ci < CIN - 1) {
            BILIN(cur ^ 1, p0a, p0b, p0c, p1a, p1b, p1c);
        }
        __syncthreads();
    }
#undef BILIN

    const int oy = y0t + yg;
    const int ox = x0t + 4 * xg;
    float* outb = g_c1 + (((size_t)b * CIN + co0 + 8 * cg) << 16) + (oy << 8) + ox;
#pragma unroll
    for (int j = 0; j < 4; j++) {
        float va[4], vb[4];
#pragma unroll
        for (int q = 0; q < 4; q++) upk2(acc[q][j], va[q], vb[q]);
        const int cr = 8 * cg + 2 * j;
        const float sa = s_scale[cr],     sha = s_shift[cr];
        const float sb = s_scale[cr + 1], shb = s_shift[cr + 1];
        float4 oa, ob;
        oa.x = fmaxf(fmaf(sa, va[0], sha), 0.f);
        oa.y = fmaxf(fmaf(sa, va[1], sha), 0.f);
        oa.z = fmaxf(fmaf(sa, va[2], sha), 0.f);
        oa.w = fmaxf(fmaf(sa, va[3], sha), 0.f);
        ob.x = fmaxf(fmaf(sb, vb[0], shb), 0.f);
        ob.y = fmaxf(fmaf(sb, vb[1], shb), 0.f);
        ob.z = fmaxf(fmaf(sb, vb[2], shb), 0.f);
        ob.w = fmaxf(fmaf(sb, vb[3], shb), 0.f);
        *(float4*)(outb + ((size_t)(2 * j)     << 16)) = oa;
        *(float4*)(outb + ((size_t)(2 * j + 1) << 16)) = ob;
    }
}

// ---------------- conv1x1(64->8) + BN + threshold + fused row-sum -----------
__global__ __launch_bounds__(256) void k_conv2rs(
    const float* __restrict__ w2,
    const float* __restrict__ gamma2, const float* __restrict__ beta2,
    const float* __restrict__ mean2, const float* __restrict__ var2)
{
    __shared__ unsigned long long s_wp[8][64];
    __shared__ float s_scale[8], s_shift[8];
    __shared__ float s_xf[8][4][264];   // data at idx 4..259; halo 2,3,260,261
    const int tid = threadIdx.x;
    const int b  = blockIdx.x >> 6;
    const int y0 = (blockIdx.x & 63) * 4;
    const int r = tid >> 6;
    const int col0 = (tid & 63) * 4;

    if (tid < 8) {
        float a = gamma2[tid] * rsqrtf(var2[tid] + 1e-5f);
        s_scale[tid] = a;
        s_shift[tid] = beta2[tid] - a * mean2[tid];
    }
    for (int i = tid; i < 512; i += 256) {
        int co = i >> 6, ci = i & 63;
        float w = w2[co * 64 + ci];
        s_wp[co][ci] = pk2(w, w);
    }
    if (tid < 128) {
        int co = tid >> 4, rr = (tid >> 2) & 3, which = tid & 3;
        const int idxs[4] = {2, 3, 260, 261};
        s_xf[co][rr][idxs[which]] = 0.f;
    }
    __syncthreads();

    const ulonglong2* c1 = (const ulonglong2*)
        (g_c1 + ((size_t)b * CIN << 16) + ((size_t)(y0 + r) << 8) + col0);
    unsigned long long a01[8], a23[8];
#pragma unroll
    for (int co = 0; co < 8; co++) { a01[co] = 0ull; a23[co] = 0ull; }
#pragma unroll 8
    for (int ci = 0; ci < CIN; ci++) {
        ulonglong2 v = c1[(size_t)ci * 16384];
#pragma unroll
        for (int co = 0; co < 8; co++) {
            unsigned long long w = s_wp[co][ci];
            FMA2(a01[co], v.x, w);
            FMA2(a23[co], v.y, w);
        }
    }

    const size_t rowoff = ((size_t)(y0 + r) << 8) + col0;
#pragma unroll
    for (int co = 0; co < 8; co++) {
        float f0, f1, f2, f3;
        upk2(a01[co], f0, f1);
        upk2(a23[co], f2, f3);
        const float sc = s_scale[co], sh = s_shift[co];
        float o0 = fmaf(sc, f0, sh), o1 = fmaf(sc, f1, sh);
        float o2 = fmaf(sc, f2, sh), o3 = fmaf(sc, f3, sh);
        float4 xf;
        xf.x = (o0 > 1.0f) ? o0 : 0.f;
        xf.y = (o1 > 1.0f) ? o1 : 0.f;
        xf.z = (o2 > 1.0f) ? o2 : 0.f;
        xf.w = (o3 > 1.0f) ? o3 : 0.f;
        *(float4*)(g_xf + (((size_t)b * COUT + co) << 16) + rowoff) = xf;
        *(float4*)&s_xf[co][r][col0 + 4] = xf;
    }
    __syncthreads();

#pragma unroll
    for (int co = 0; co < 8; co++) {
        const float* f = &s_xf[co][r][col0 + 2];
        float4 s;
        s.x = f[0] + f[1] + f[2] + f[3] + f[4];
        s.y = f[1] + f[2] + f[3] + f[4] + f[5];
        s.z = f[2] + f[3] + f[4] + f[5] + f[6];
        s.w = f[3] + f[4] + f[5] + f[6] + f[7];
        *(float4*)(g_rs + (((size_t)b * COUT + co) << 16) + rowoff) = s;
    }
}

// ---------------- fused ws + rowmax + NMS + per-segment top-8 ---------------
// block = (plane, 16-row segment). ws/rm live only in smem.
__global__ __launch_bounds__(256) void k_nms() {
    __shared__ __align__(16) float s_rs[24][256];   // aliased by s_rm after use
    __shared__ __align__(16) float s_ws[20][260];   // data cols 2..257; halo -1
    float (*s_rm)[256] = (float (*)[256])&s_rs[0][0];
    unsigned long long* s_keys = (unsigned long long*)&s_ws[0][0];

    const int bid = blockIdx.x;
    const int pl = bid >> 4;
    const int seg = bid & 15;
    const int y0 = seg * 16;
    const int x = threadIdx.x;
    const float* rs = g_rs + ((size_t)pl << 16);

#pragma unroll
    for (int i = 0; i < 24; i++) {
        int row = y0 - 4 + i;
        s_rs[i][x] = (row >= 0 && row < 256) ? rs[(row << 8) + x] : 0.f;
    }
    if (x < 80) {
        int rr = x >> 2, which = x & 3;
        const int idxs[4] = {0, 1, 258, 259};
        s_ws[rr][idxs[which]] = -1.f;
    }
    __syncthreads();

    // ws rows y0-2 .. y0+17 (OOB rows = -1, matching -inf pad semantics)
#pragma unroll
    for (int i = 0; i < 20; i++) {
        int y = y0 - 2 + i;
        float w;
        if (y >= 0 && y < 256)
            w = s_rs[i][x] + s_rs[i + 1][x] + s_rs[i + 2][x]
              + s_rs[i + 3][x] + s_rs[i + 4][x];
        else
            w = -1.f;
        s_ws[i][x + 2] = w;
    }
    __syncthreads();   // s_rs reads done -> s_rm may overwrite

#pragma unroll
    for (int i = 0; i < 20; i++) {
        const float* wr = &s_ws[i][x];
        s_rm[i][x] = fmaxf(fmaxf(fmaxf(wr[0], wr[1]), fmaxf(wr[2], wr[3])), wr[4]);
    }
    __syncthreads();

    unsigned long long k[8];
#pragma unroll
    for (int j = 0; j < 8; j++) k[j] = 0ull;

#pragma unroll
    for (int i = 0; i < 16; i++) {
        float m = fmaxf(fmaxf(fmaxf(s_rm[i][x], s_rm[i + 1][x]),
                              fmaxf(s_rm[i + 2][x], s_rm[i + 3][x])),
                        s_rm[i + 4][x]);
        float v = s_ws[i + 2][x + 2];
        if (v == m) {
            unsigned pos = (unsigned)(((y0 + i) << 8) + x);
            unsigned long long key =
                ((unsigned long long)__float_as_uint(v) << 32) | (unsigned)(~pos);
            if (key > k[7]) {
                int p = 7;
#pragma unroll
                for (int q = 7; q > 0; q--) {
                    if (key > k[q - 1]) { k[q] = k[q - 1]; p = q - 1; }
                }
                k[p] = key;
            }
        }
    }
    __syncthreads();   // s_ws reads done -> s_keys may overwrite

#pragma unroll
    for (int j = 0; j < 8; j++) s_keys[x * 8 + j] = k[j];
    __syncthreads();

    for (int off = 128; off > 0; off >>= 1) {
        if (x < off) {
            unsigned long long* a = &s_keys[x * 8];
            unsigned long long* b = &s_keys[(x + off) * 8];
            unsigned long long out[8];
            int i = 0, j = 0;
#pragma unroll
            for (int t = 0; t < 8; t++)
                out[t] = (a[i] >= b[j]) ? a[i++] : b[j++];
#pragma unroll
            for (int t = 0; t < 8; t++) a[t] = out[t];
        }
        __syncthreads();
    }
    if (x < 8) g_seg[bid * 8 + x] = s_keys[x];
}

// ---------------- top-k stage 2 (merge NSEG*8 keys) + fused gather ----------
__global__ __launch_bounds__(128) void k_topk2(float* __restrict__ out) {
    __shared__ unsigned long long s[NSEG * 8];
    __shared__ unsigned long long top[8];
    const int bc = blockIdx.x;
    const int tid = threadIdx.x;

    s[tid] = g_seg[bc * (NSEG * 8) + tid];
    __syncthreads();

    if (tid == 0) {
        unsigned long long k[8];
#pragma unroll
        for (int j = 0; j < 8; j++) k[j] = 0ull;
        for (int i = 0; i < NSEG * 8; i++) {
            unsigned long long key = s[i];
            if (key > k[7]) {
                int p = 7;
#pragma unroll
                for (int q = 7; q > 0; q--) {
                    if (key > k[q - 1]) { k[q] = k[q - 1]; p = q - 1; }
                }
                k[p] = key;
            }
        }
#pragma unroll
        for (int j = 0; j < 8; j++) top[j] = k[j];
    }
    __syncthreads();

    if (tid < 8) {
        unsigned pos = ~(unsigned)(top[tid] & 0xFFFFFFFFull);
        int h = pos >> 8, w = pos & 255;
        const int gid = bc * 8 + tid;
        const float* xf = g_xf + (size_t)bc * PLANE;
        float* po = out + gid * 25;
#pragma unroll
        for (int dy = 0; dy < 5; dy++) {
            int yy = h + dy - 2;
#pragma unroll
            for (int dx = 0; dx < 5; dx++) {
                int xx = w + dx - 2;
                float v = 0.f;
                if (yy >= 0 && yy < 256 && xx >= 0 && xx < 256) v = xf[yy * 256 + xx];
                po[dy * 5 + dx] = v;
            }
        }
        float* pp = out + B_ * COUT * NUM_ * 25 + gid * 4;
        pp[0] = (float)min(max(w - 2, 0), 255);
        pp[1] = (float)min(max(h - 2, 0), 255);
        pp[2] = (float)min(max(w + 2, 0), 255);
        pp[3] = (float)min(max(h + 2, 0), 255);
    }
}

// ---------------- launch ------------------------------------------------------
extern "C" void kernel_launch(void* const* d_in, const int* in_sizes, int n_in,
                              void* d_out, int out_size) {
    const float* x      = (const float*)d_in[0];
    const float* w1     = (const float*)d_in[1];
    const float* b1     = (const float*)d_in[2];
    const float* gamma1 = (const float*)d_in[3];
    const float* beta1  = (const float*)d_in[4];
    const float* mean1  = (const float*)d_in[5];
    const float* var1   = (const float*)d_in[6];
    const float* w2     = (const float*)d_in[7];
    const float* gamma2 = (const float*)d_in[8];
    const float* beta2  = (const float*)d_in[9];
    const float* mean2  = (const float*)d_in[10];
    const float* var2   = (const float*)d_in[11];
    float* out = (float*)d_out;

    dim3 cg(2, 64, B_ * 4);
    k_conv1<<<cg, 256>>>(x, w1, b1, gamma1, beta1, mean1, var1);

    k_conv2rs<<<B_ * 64, 256>>>(w2, gamma2, beta2, mean2, var2);

    k_nms<<<B_ * COUT * NSEG, 256>>>();
    k_topk2<<<B_ * COUT, NSEG * 8>>>(out);
}

// round 10
// speedup vs baseline: 1.0839x; 1.0077x over previous
#include <cuda_runtime.h>
#include <cstdint>

#define B_   8
#define CIN  64
#define COUT 8
#define H1   128
#define W1   128
#define H2   256
#define W2   256
#define PLANE (H2*W2)   /* 65536 */
#define NUM_ 8
#define NSEG 16

// ---------------- scratch (device globals; no allocation allowed) ----------
__device__ float g_p  [(size_t)4*B_*COUT*PLANE]; // conv2 partials per quarter
__device__ float g_xf [(size_t)B_*COUT*PLANE];   // conv2+BN, thresholded
__device__ float g_rs [(size_t)B_*COUT*PLANE];   // row sums
__device__ unsigned long long g_seg[B_*COUT*NSEG*8]; // per-segment top-8 keys

// ---------------- packed f32x2 helpers --------------------------------------
__device__ __forceinline__ unsigned long long pk2(float lo, float hi) {
    unsigned long long r;
    asm("mov.b64 %0, {%1, %2};" : "=l"(r) : "f"(lo), "f"(hi));
    return r;
}
__device__ __forceinline__ void upk2(unsigned long long v, float& lo, float& hi) {
    asm("mov.b64 {%0, %1}, %2;" : "=f"(lo), "=f"(hi) : "l"(v));
}
#define FMA2(d, a, b) asm("fma.rn.f32x2 %0, %1, %2, %0;" : "+l"(d) : "l"(a), "l"(b))

// ============================================================================
// conv1: fused bilinear-2x-upsample + conv3x3(64->64) + bias + BN + ReLU
//        + per-quarter partial of conv1x1 (writes g_p, never materializes c1)
// ============================================================================
__global__ __launch_bounds__(256, 3) void k_conv1(
    const float* __restrict__ x,
    const float* __restrict__ w1, const float* __restrict__ b1,
    const float* __restrict__ gamma1, const float* __restrict__ beta1,
    const float* __restrict__ mean1, const float* __restrict__ var1,
    const float* __restrict__ w2)
{
    __shared__ __align__(16) unsigned long long s_w[CIN][9][8]; // [ci][tap][pair]
    __shared__ float s_in[2][6][136];
    __shared__ float s_scale[16], s_shift[16];
    __shared__ unsigned long long s_w2[8][16];   // (w,w) dup, quarter slice

    const int tid = threadIdx.x;
    const int xg = tid & 31;
    const int yg = (tid >> 5) & 3;
    const int cg = tid >> 7;
    const int bz  = blockIdx.z;
    const int b   = bz >> 2;
    const int qtr = bz & 3;
    const int co0 = qtr * 16;
    const int x0t = blockIdx.x * 128;
    const int y0t = blockIdx.y * 4;

    const float* xb = x + (size_t)b * CIN * (H1 * W1);

    for (int i = tid; i < CIN * 9 * 8; i += 256) {
        int cp = i & 7; int rest = i >> 3;
        int p = rest % 9; int ci = rest / 9;
        int coA = co0 + 2 * cp;
        float wa = w1[((size_t)coA       * CIN + ci) * 9 + p];
        float wb = w1[((size_t)(coA + 1) * CIN + ci) * 9 + p];
        s_w[ci][p][cp] = pk2(wa, wb);
    }
    if (tid < 16) {
        int co = co0 + tid;
        float a = gamma1[co] * rsqrtf(var1[co] + 1e-5f);
        s_scale[tid] = a;
        s_shift[tid] = fmaf(a, b1[co] - mean1[co], beta1[co]);
    }
    if (tid < 128) {
        int co2 = tid >> 4, j = tid & 15;
        float w = w2[co2 * 64 + co0 + j];
        s_w2[co2][j] = pk2(w, w);
    }

    const bool runA = tid < 198;
    const int ur  = tid / 33;
    const int c0r = (tid - ur * 33) * 4;
    const int gy  = y0t + ur - 1;
    const int gx0 = x0t + c0r - 1;
    const int sy  = (gy - 1) >> 1;
    const int ro0 = min(max(sy, 0), H1 - 1) * W1;
    const int ro1 = min(max(sy + 1, 0), H1 - 1) * W1;
    const float wyv = (gy & 1) ? 0.25f : 0.75f;
    const int S   = (gx0 - 1) >> 1;
    const int cS0 = min(max(S, 0), W1 - 1);
    const int cS1 = min(max(S + 1, 0), W1 - 1);
    const int cS2 = min(max(S + 2, 0), W1 - 1);
    const bool rowOK = (gy >= 0) && (gy < H2);
    bool mok[4];
#pragma unroll
    for (int j = 0; j < 4; j++) {
        int gx = gx0 + j;
        mok[j] = rowOK && (gx >= 0) && (gx < W2);
    }

#define BILIN(buf, p0a, p0b, p0c, p1a, p1b, p1c) do {                         \
        float t0 = p0a + 0.25f * (p0b - p0a);                                 \
        float t1 = p0a + 0.75f * (p0b - p0a);                                 \
        float t2 = p0b + 0.25f * (p0c - p0b);                                 \
        float t3 = p0b + 0.75f * (p0c - p0b);                                 \
        float u0 = p1a + 0.25f * (p1b - p1a);                                 \
        float u1 = p1a + 0.75f * (p1b - p1a);                                 \
        float u2 = p1b + 0.25f * (p1c - p1b);                                 \
        float u3 = p1b + 0.75f * (p1c - p1b);                                 \
        float4 o;                                                             \
        o.x = mok[0] ? (t0 + wyv * (u0 - t0)) : 0.f;                          \
        o.y = mok[1] ? (t1 + wyv * (u1 - t1)) : 0.f;                          \
        o.z = mok[2] ? (t2 + wyv * (u2 - t2)) : 0.f;                          \
        o.w = mok[3] ? (t3 + wyv * (u3 - t3)) : 0.f;                          \
        *(float4*)&s_in[buf][ur][c0r] = o;                                    \
    } while (0)

    if (runA) {
        const float* xp = xb;
        float a0 = xp[ro0 + cS0], a1 = xp[ro0 + cS1], a2 = xp[ro0 + cS2];
        float b0 = xp[ro1 + cS0], b1v = xp[ro1 + cS1], b2 = xp[ro1 + cS2];
        BILIN(0, a0, a1, a2, b0, b1v, b2);
    }
    __syncthreads();

    unsigned long long acc[4][4];
#pragma unroll
    for (int q = 0; q < 4; q++)
#pragma unroll
        for (int j = 0; j < 4; j++) acc[q][j] = 0ull;

    for (int ci = 0; ci < CIN; ci++) {
        const int cur = ci & 1;

        float p0a, p0b, p0c, p1a, p1b, p1c;
        if (runA && ci < CIN - 1) {
            const float* xp = xb + ((size_t)(ci + 1) << 14);
            p0a = xp[ro0 + cS0]; p0b = xp[ro0 + cS1]; p0c = xp[ro0 + cS2];
            p1a = xp[ro1 + cS0]; p1b = xp[ro1 + cS1]; p1c = xp[ro1 + cS2];
        }

#pragma unroll
        for (int kr = 0; kr < 3; kr++) {
            const float* row = &s_in[cur][yg + kr][4 * xg];
            float4 F = *(const float4*)row;
            float2 G = *(const float2*)(row + 4);
            unsigned long long Q[6];
            Q[0] = pk2(F.x, F.x);
            Q[1] = pk2(F.y, F.y);
            Q[2] = pk2(F.z, F.z);
            Q[3] = pk2(F.w, F.w);
            Q[4] = pk2(G.x, G.x);
            Q[5] = pk2(G.y, G.y);
#pragma unroll
            for (int kc = 0; kc < 3; kc++) {
                const ulonglong2* wrow =
                    (const ulonglong2*)&s_w[ci][kr * 3 + kc][cg * 4];
                ulonglong2 wA = wrow[0];
                ulonglong2 wB = wrow[1];
#pragma unroll
                for (int q = 0; q < 4; q++) {
                    unsigned long long iv = Q[kc + q];
                    FMA2(acc[q][0], iv, wA.x);
                    FMA2(acc[q][1], iv, wA.y);
                    FMA2(acc[q][2], iv, wB.x);
                    FMA2(acc[q][3], iv, wB.y);
                }
            }
        }

        if (runA && ci < CIN - 1) {
            BILIN(cur ^ 1, p0a, p0b, p0c, p1a, p1b, p1c);
        }
        __syncthreads();
    }
#undef BILIN

    // ---- epilogue 1: BN + ReLU, stage vals in smem (overlay s_w, now dead)
    float4* s_vals = (float4*)&s_w[0][0][0];   // [16 ci][128 slots] float4
    const int slot = tid & 127;
#pragma unroll
    for (int j = 0; j < 4; j++) {
        float va[4], vb[4];
#pragma unroll
        for (int q = 0; q < 4; q++) upk2(acc[q][j], va[q], vb[q]);
        const int cr = 8 * cg + 2 * j;
        const float sa = s_scale[cr],     sha = s_shift[cr];
        const float sb = s_scale[cr + 1], shb = s_shift[cr + 1];
        float4 oa, ob;
        oa.x = fmaxf(fmaf(sa, va[0], sha), 0.f);
        oa.y = fmaxf(fmaf(sa, va[1], sha), 0.f);
        oa.z = fmaxf(fmaf(sa, va[2], sha), 0.f);
        oa.w = fmaxf(fmaf(sa, va[3], sha), 0.f);
        ob.x = fmaxf(fmaf(sb, vb[0], shb), 0.f);
        ob.y = fmaxf(fmaf(sb, vb[1], shb), 0.f);
        ob.z = fmaxf(fmaf(sb, vb[2], shb), 0.f);
        ob.w = fmaxf(fmaf(sb, vb[3], shb), 0.f);
        s_vals[cr * 128 + slot]       = oa;
        s_vals[(cr + 1) * 128 + slot] = ob;
    }
    __syncthreads();

    // ---- epilogue 2: partial conv1x1 over this quarter's 16 channels -------
    // cg0 -> co2 0..3, cg1 -> co2 4..7; FFMA2 over px pairs, j ascending.
    const int c2b = 4 * cg;
    unsigned long long p01[4], p23[4];
#pragma unroll
    for (int c = 0; c < 4; c++) { p01[c] = 0ull; p23[c] = 0ull; }
#pragma unroll
    for (int j = 0; j < 16; j++) {
        float4 v = s_vals[j * 128 + slot];
        unsigned long long i01 = pk2(v.x, v.y);
        unsigned long long i23 = pk2(v.z, v.w);
#pragma unroll
        for (int c = 0; c < 4; c++) {
            unsigned long long w = s_w2[c2b + c][j];
            FMA2(p01[c], i01, w);
            FMA2(p23[c], i23, w);
        }
    }

    const int oy = y0t + yg;
    const int ox = x0t + 4 * xg;
    float* pp = g_p + (((size_t)(qtr * B_ + b) * 8 + c2b) << 16) + (oy << 8) + ox;
#pragma unroll
    for (int c = 0; c < 4; c++) {
        float f0, f1, f2, f3;
        upk2(p01[c], f0, f1);
        upk2(p23[c], f2, f3);
        *(float4*)(pp + ((size_t)c << 16)) = make_float4(f0, f1, f2, f3);
    }
}

// ---------------- sum 4 quarter-partials + BN2 + threshold + row-sum --------
__global__ __launch_bounds__(256) void k_sum4(
    const float* __restrict__ gamma2, const float* __restrict__ beta2,
    const float* __restrict__ mean2, const float* __restrict__ var2)
{
    __shared__ float s_scale[8], s_shift[8];
    __shared__ float s_xf[8][4][264];   // data at idx 4..259; halo 2,3,260,261
    const int tid = threadIdx.x;
    const int b  = blockIdx.x >> 6;
    const int y0 = (blockIdx.x & 63) * 4;
    const int r = tid >> 6;
    const int col0 = (tid & 63) * 4;

    if (tid < 8) {
        float a = gamma2[tid] * rsqrtf(var2[tid] + 1e-5f);
        s_scale[tid] = a;
        s_shift[tid] = beta2[tid] - a * mean2[tid];
    }
    if (tid < 128) {
        int co = tid >> 4, rr = (tid >> 2) & 3, which = tid & 3;
        const int idxs[4] = {2, 3, 260, 261};
        s_xf[co][rr][idxs[which]] = 0.f;
    }
    __syncthreads();

    const size_t rowoff = ((size_t)(y0 + r) << 8) + col0;
#pragma unroll
    for (int co = 0; co < 8; co++) {
        float4 p0 = *(const float4*)(g_p + (((size_t)(0 * B_ + b) * 8 + co) << 16) + rowoff);
        float4 p1 = *(const float4*)(g_p + (((size_t)(1 * B_ + b) * 8 + co) << 16) + rowoff);
        float4 p2 = *(const float4*)(g_p + (((size_t)(2 * B_ + b) * 8 + co) << 16) + rowoff);
        float4 p3 = *(const float4*)(g_p + (((size_t)(3 * B_ + b) * 8 + co) << 16) + rowoff);
        float sx = ((p0.x + p1.x) + p2.x) + p3.x;
        float sy = ((p0.y + p1.y) + p2.y) + p3.y;
        float sz = ((p0.z + p1.z) + p2.z) + p3.z;
        float sw = ((p0.w + p1.w) + p2.w) + p3.w;
        const float sc = s_scale[co], sh = s_shift[co];
        float o0 = fmaf(sc, sx, sh), o1 = fmaf(sc, sy, sh);
        float o2 = fmaf(sc, sz, sh), o3 = fmaf(sc, sw, sh);
        float4 xf;
        xf.x = (o0 > 1.0f) ? o0 : 0.f;
        xf.y = (o1 > 1.0f) ? o1 : 0.f;
        xf.z = (o2 > 1.0f) ? o2 : 0.f;
        xf.w = (o3 > 1.0f) ? o3 : 0.f;
        *(float4*)(g_xf + (((size_t)b * COUT + co) << 16) + rowoff) = xf;
        *(float4*)&s_xf[co][r][col0 + 4] = xf;
    }
    __syncthreads();

#pragma unroll
    for (int co = 0; co < 8; co++) {
        const float* f = &s_xf[co][r][col0 + 2];
        float4 s;
        s.x = f[0] + f[1] + f[2] + f[3] + f[4];
        s.y = f[1] + f[2] + f[3] + f[4] + f[5];
        s.z = f[2] + f[3] + f[4] + f[5] + f[6];
        s.w = f[3] + f[4] + f[5] + f[6] + f[7];
        *(float4*)(g_rs + (((size_t)b * COUT + co) << 16) + rowoff) = s;
    }
}

// ---------------- fused ws + rowmax + NMS + per-segment top-8 ---------------
__global__ __launch_bounds__(256) void k_nms() {
    __shared__ __align__(16) float s_rs[24][256];   // aliased by s_rm after use
    __shared__ __align__(16) float s_ws[20][260];   // data cols 2..257; halo -1
    float (*s_rm)[256] = (float (*)[256])&s_rs[0][0];
    unsigned long long* s_keys = (unsigned long long*)&s_ws[0][0];

    const int bid = blockIdx.x;
    const int pl = bid >> 4;
    const int seg = bid & 15;
    const int y0 = seg * 16;
    const int x = threadIdx.x;
    const float* rs = g_rs + ((size_t)pl << 16);

#pragma unroll
    for (int i = 0; i < 24; i++) {
        int row = y0 - 4 + i;
        s_rs[i][x] = (row >= 0 && row < 256) ? rs[(row << 8) + x] : 0.f;
    }
    if (x < 80) {
        int rr = x >> 2, which = x & 3;
        const int idxs[4] = {0, 1, 258, 259};
        s_ws[rr][idxs[which]] = -1.f;
    }
    __syncthreads();

#pragma unroll
    for (int i = 0; i < 20; i++) {
        int y = y0 - 2 + i;
        float w;
        if (y >= 0 && y < 256)
            w = s_rs[i][x] + s_rs[i + 1][x] + s_rs[i + 2][x]
              + s_rs[i + 3][x] + s_rs[i + 4][x];
        else
            w = -1.f;
        s_ws[i][x + 2] = w;
    }
    __syncthreads();

#pragma unroll
    for (int i = 0; i < 20; i++) {
        const float* wr = &s_ws[i][x];
        s_rm[i][x] = fmaxf(fmaxf(fmaxf(wr[0], wr[1]), fmaxf(wr[2], wr[3])), wr[4]);
    }
    __syncthreads();

    unsigned long long k[8];
#pragma unroll
    for (int j = 0; j < 8; j++) k[j] = 0ull;

#pragma unroll
    for (int i = 0; i < 16; i++) {
        float m = fmaxf(fmaxf(fmaxf(s_rm[i][x], s_rm[i + 1][x]),
                              fmaxf(s_rm[i + 2][x], s_rm[i + 3][x])),
                        s_rm[i + 4][x]);
        float v = s_ws[i + 2][x + 2];
        if (v == m) {
            unsigned pos = (unsigned)(((y0 + i) << 8) + x);
            unsigned long long key =
                ((unsigned long long)__float_as_uint(v) << 32) | (unsigned)(~pos);
            if (key > k[7]) {
                int p = 7;
#pragma unroll
                for (int q = 7; q > 0; q--) {
                    if (key > k[q - 1]) { k[q] = k[q - 1]; p = q - 1; }
                }
                k[p] = key;
            }
        }
    }
    __syncthreads();

#pragma unroll
    for (int j = 0; j < 8; j++) s_keys[x * 8 + j] = k[j];
    __syncthreads();

    for (int off = 128; off > 0; off >>= 1) {
        if (x < off) {
            unsigned long long* a = &s_keys[x * 8];
            unsigned long long* b = &s_keys[(x + off) * 8];
            unsigned long long out[8];
            int i = 0, j = 0;
#pragma unroll
            for (int t = 0; t < 8; t++)
                out[t] = (a[i] >= b[j]) ? a[i++] : b[j++];
#pragma unroll
            for (int t = 0; t < 8; t++) a[t] = out[t];
        }
        __syncthreads();
    }
    if (x < 8) g_seg[bid * 8 + x] = s_keys[x];
}

// ---------------- top-k stage 2: parallel merge + spread gather -------------
__global__ __launch_bounds__(224) void k_topk2(float* __restrict__ out) {
    __shared__ unsigned long long s[NSEG * 8];
    const int bc = blockIdx.x;
    const int tid = threadIdx.x;

    if (tid < NSEG * 8) s[tid] = g_seg[bc * (NSEG * 8) + tid];
    __syncthreads();

    for (int off = NSEG / 2; off > 0; off >>= 1) {
        if (tid < off) {
            unsigned long long* a = &s[tid * 8];
            unsigned long long* b = &s[(tid + off) * 8];
            unsigned long long m[8];
            int i = 0, j = 0;
#pragma unroll
            for (int t = 0; t < 8; t++)
                m[t] = (a[i] >= b[j]) ? a[i++] : b[j++];
#pragma unroll
            for (int t = 0; t < 8; t++) a[t] = m[t];
        }
        __syncthreads();
    }
    // s[0..7] = global top-8 keys

    if (tid < 200) {
        const int slotk = tid / 25;
        const int e = tid - slotk * 25;
        unsigned pos = ~(unsigned)(s[slotk] & 0xFFFFFFFFull);
        int h = pos >> 8, w = pos & 255;
        int yy = h + e / 5 - 2;
        int xx = w + e % 5 - 2;
        float v = 0.f;
        if (yy >= 0 && yy < 256 && xx >= 0 && xx < 256)
            v = g_xf[((size_t)bc << 16) + (yy << 8) + xx];
        out[(bc * 8 + slotk) * 25 + e] = v;
    }
    if (tid < 32) {
        const int slotk = tid >> 2;
        const int c = tid & 3;
        unsigned pos = ~(unsigned)(s[slotk] & 0xFFFFFFFFull);
        int h = pos >> 8, w = pos & 255;
        int val;
        if (c == 0)      val = min(max(w - 2, 0), 255);
        else if (c == 1) val = min(max(h - 2, 0), 255);
        else if (c == 2) val = min(max(w + 2, 0), 255);
        else             val = min(max(h + 2, 0), 255);
        out[B_ * COUT * NUM_ * 25 + (bc * 8 + slotk) * 4 + c] = (float)val;
    }
}

// ---------------- launch ------------------------------------------------------
extern "C" void kernel_launch(void* const* d_in, const int* in_sizes, int n_in,
                              void* d_out, int out_size) {
    const float* x      = (const float*)d_in[0];
    const float* w1     = (const float*)d_in[1];
    const float* b1     = (const float*)d_in[2];
    const float* gamma1 = (const float*)d_in[3];
    const float* beta1  = (const float*)d_in[4];
    const float* mean1  = (const float*)d_in[5];
    const float* var1   = (const float*)d_in[6];
    const float* w2     = (const float*)d_in[7];
    const float* gamma2 = (const float*)d_in[8];
    const float* beta2  = (const float*)d_in[9];
    const float* mean2  = (const float*)d_in[10];
    const float* var2   = (const float*)d_in[11];
    float* out = (float*)d_out;

    dim3 cg(2, 64, B_ * 4);
    k_conv1<<<cg, 256>>>(x, w1, b1, gamma1, beta1, mean1, var1, w2);

    k_sum4<<<B_ * 64, 256>>>(gamma2, beta2, mean2, var2);

    k_nms<<<B_ * COUT * NSEG, 256>>>();
    k_topk2<<<B_ * COUT, 224>>>(out);
}

// round 11
// speedup vs baseline: 1.1907x; 1.0985x over previous
#include <cuda_runtime.h>
#include <cstdint>

#define B_   8
#define CIN  64
#define COUT 8
#define H1   128
#define W1   128
#define H2   256
#define W2   256
#define PLANE (H2*W2)   /* 65536 */
#define NUM_ 8
#define NSEG 16

// ---------------- scratch (device globals; no allocation allowed) ----------
__device__ float g_p  [(size_t)2*B_*COUT*PLANE]; // conv2 partials per half
__device__ float g_xf [(size_t)B_*COUT*PLANE];   // conv2+BN, thresholded
__device__ float g_rs [(size_t)B_*COUT*PLANE];   // row sums
__device__ unsigned long long g_seg[B_*COUT*NSEG*8]; // per-segment top-8 keys

// ---------------- packed f32x2 helpers --------------------------------------
__device__ __forceinline__ unsigned long long pk2(float lo, float hi) {
    unsigned long long r;
    asm("mov.b64 %0, {%1, %2};" : "=l"(r) : "f"(lo), "f"(hi));
    return r;
}
__device__ __forceinline__ void upk2(unsigned long long v, float& lo, float& hi) {
    asm("mov.b64 {%0, %1}, %2;" : "=f"(lo), "=f"(hi) : "l"(v));
}
#define FMA2(d, a, b) asm("fma.rn.f32x2 %0, %1, %2, %0;" : "+l"(d) : "l"(a), "l"(b))

// dynamic smem layout for conv1
#define C1_W_BYTES    (CIN * 9 * 16 * 8)            /* 73728 */
#define C1_IN_BYTES   (2 * 6 * 136 * 4)             /* 6528  */
#define C1_W2_BYTES   (8 * 32 * 8)                  /* 2048  */
#define C1_SS_BYTES   (2 * 32 * 4)                  /* 256   */
#define C1_SMEM_TOTAL (C1_W_BYTES + C1_IN_BYTES + C1_W2_BYTES + C1_SS_BYTES)

// ============================================================================
// conv1: fused bilinear-2x-upsample + conv3x3(64->64) + bias + BN + ReLU
//        + per-half partial of conv1x1 (writes g_p, never materializes c1)
// grid (2, 64, B*2): tile 128(w) x 4(h), 32-co half per block.
// block 256 = 32 xg * 4 yg * 2 cg; thread: 4 px * 16 co (8 pairs, FFMA2).
// ============================================================================
__global__ __launch_bounds__(256, 2) void k_conv1(
    const float* __restrict__ x,
    const float* __restrict__ w1, const float* __restrict__ b1,
    const float* __restrict__ gamma1, const float* __restrict__ beta1,
    const float* __restrict__ mean1, const float* __restrict__ var1,
    const float* __restrict__ w2)
{
    extern __shared__ __align__(16) unsigned char dsm[];
    unsigned long long (*s_w)[9][16] =
        (unsigned long long (*)[9][16])(dsm);                    // [ci][tap][pair]
    float (*s_in)[6][136] = (float (*)[6][136])(dsm + C1_W_BYTES);
    unsigned long long (*s_w2)[32] =
        (unsigned long long (*)[32])(dsm + C1_W_BYTES + C1_IN_BYTES);
    float* s_scale = (float*)(dsm + C1_W_BYTES + C1_IN_BYTES + C1_W2_BYTES);
    float* s_shift = s_scale + 32;

    const int tid = threadIdx.x;
    const int xg = tid & 31;
    const int yg = (tid >> 5) & 3;
    const int cg = tid >> 7;               // 0/1: which 16-co group of the 32
    const int bz  = blockIdx.z;
    const int b    = bz >> 1;
    const int half = bz & 1;
    const int co0 = half * 32;
    const int x0t = blockIdx.x * 128;
    const int y0t = blockIdx.y * 4;

    const float* xb = x + (size_t)b * CIN * (H1 * W1);

    for (int i = tid; i < CIN * 9 * 16; i += 256) {
        int cp = i & 15; int rest = i >> 4;
        int p = rest % 9; int ci = rest / 9;
        int coA = co0 + 2 * cp;
        float wa = w1[((size_t)coA       * CIN + ci) * 9 + p];
        float wb = w1[((size_t)(coA + 1) * CIN + ci) * 9 + p];
        s_w[ci][p][cp] = pk2(wa, wb);
    }
    if (tid < 32) {
        int co = co0 + tid;
        float a = gamma1[co] * rsqrtf(var1[co] + 1e-5f);
        s_scale[tid] = a;
        s_shift[tid] = fmaf(a, b1[co] - mean1[co], beta1[co]);
    }
    {   // s_w2: exactly 256 entries (8 co2 x 32 ci-of-half)
        int co2 = tid >> 5, j = tid & 31;
        float w = w2[co2 * 64 + co0 + j];
        s_w2[co2][j] = pk2(w, w);
    }

    const bool runA = tid < 198;
    const int ur  = tid / 33;
    const int c0r = (tid - ur * 33) * 4;
    const int gy  = y0t + ur - 1;
    const int gx0 = x0t + c0r - 1;
    const int sy  = (gy - 1) >> 1;
    const int ro0 = min(max(sy, 0), H1 - 1) * W1;
    const int ro1 = min(max(sy + 1, 0), H1 - 1) * W1;
    const float wyv = (gy & 1) ? 0.25f : 0.75f;
    const int S   = (gx0 - 1) >> 1;
    const int cS0 = min(max(S, 0), W1 - 1);
    const int cS1 = min(max(S + 1, 0), W1 - 1);
    const int cS2 = min(max(S + 2, 0), W1 - 1);
    const bool rowOK = (gy >= 0) && (gy < H2);
    bool mok[4];
#pragma unroll
    for (int j = 0; j < 4; j++) {
        int gx = gx0 + j;
        mok[j] = rowOK && (gx >= 0) && (gx < W2);
    }

#define BILIN(buf, p0a, p0b, p0c, p1a, p1b, p1c) do {                         \
        float t0 = p0a + 0.25f * (p0b - p0a);                                 \
        float t1 = p0a + 0.75f * (p0b - p0a);                                 \
        float t2 = p0b + 0.25f * (p0c - p0b);                                 \
        float t3 = p0b + 0.75f * (p0c - p0b);                                 \
        float u0 = p1a + 0.25f * (p1b - p1a);                                 \
        float u1 = p1a + 0.75f * (p1b - p1a);                                 \
        float u2 = p1b + 0.25f * (p1c - p1b);                                 \
        float u3 = p1b + 0.75f * (p1c - p1b);                                 \
        float4 o;                                                             \
        o.x = mok[0] ? (t0 + wyv * (u0 - t0)) : 0.f;                          \
        o.y = mok[1] ? (t1 + wyv * (u1 - t1)) : 0.f;                          \
        o.z = mok[2] ? (t2 + wyv * (u2 - t2)) : 0.f;                          \
        o.w = mok[3] ? (t3 + wyv * (u3 - t3)) : 0.f;                          \
        *(float4*)&s_in[buf][ur][c0r] = o;                                    \
    } while (0)

    if (runA) {
        const float* xp = xb;
        float a0 = xp[ro0 + cS0], a1 = xp[ro0 + cS1], a2 = xp[ro0 + cS2];
        float b0 = xp[ro1 + cS0], b1v = xp[ro1 + cS1], b2 = xp[ro1 + cS2];
        BILIN(0, a0, a1, a2, b0, b1v, b2);
    }
    __syncthreads();

    unsigned long long acc[4][8];
#pragma unroll
    for (int q = 0; q < 4; q++)
#pragma unroll
        for (int j = 0; j < 8; j++) acc[q][j] = 0ull;

    for (int ci = 0; ci < CIN; ci++) {
        const int cur = ci & 1;

        float p0a, p0b, p0c, p1a, p1b, p1c;
        if (runA && ci < CIN - 1) {
            const float* xp = xb + ((size_t)(ci + 1) << 14);
            p0a = xp[ro0 + cS0]; p0b = xp[ro0 + cS1]; p0c = xp[ro0 + cS2];
            p1a = xp[ro1 + cS0]; p1b = xp[ro1 + cS1]; p1c = xp[ro1 + cS2];
        }

#pragma unroll
        for (int kr = 0; kr < 3; kr++) {
            const float* row = &s_in[cur][yg + kr][4 * xg];
            float4 F = *(const float4*)row;
            float2 G = *(const float2*)(row + 4);
            unsigned long long Q[6];
            Q[0] = pk2(F.x, F.x);
            Q[1] = pk2(F.y, F.y);
            Q[2] = pk2(F.z, F.z);
            Q[3] = pk2(F.w, F.w);
            Q[4] = pk2(G.x, G.x);
            Q[5] = pk2(G.y, G.y);
#pragma unroll
            for (int kc = 0; kc < 3; kc++) {
                const ulonglong2* wrow =
                    (const ulonglong2*)&s_w[ci][kr * 3 + kc][cg * 8];
                ulonglong2 wA = wrow[0];
                ulonglong2 wB = wrow[1];
                ulonglong2 wC = wrow[2];
                ulonglong2 wD = wrow[3];
#pragma unroll
                for (int q = 0; q < 4; q++) {
                    unsigned long long iv = Q[kc + q];
                    FMA2(acc[q][0], iv, wA.x);
                    FMA2(acc[q][1], iv, wA.y);
                    FMA2(acc[q][2], iv, wB.x);
                    FMA2(acc[q][3], iv, wB.y);
                    FMA2(acc[q][4], iv, wC.x);
                    FMA2(acc[q][5], iv, wC.y);
                    FMA2(acc[q][6], iv, wD.x);
                    FMA2(acc[q][7], iv, wD.y);
                }
            }
        }

        if (runA && ci < CIN - 1) {
            BILIN(cur ^ 1, p0a, p0b, p0c, p1a, p1b, p1c);
        }
        __syncthreads();
    }
#undef BILIN

    // ---- epilogue 1: BN + ReLU, stage vals in smem (overlay s_w, now dead)
    float4* s_vals = (float4*)&s_w[0][0][0];   // [32 ci][128 slots] float4 (64KB)
    const int slot = tid & 127;
#pragma unroll
    for (int j = 0; j < 8; j++) {
        float va[4], vb[4];
#pragma unroll
        for (int q = 0; q < 4; q++) upk2(acc[q][j], va[q], vb[q]);
        const int cr = 16 * cg + 2 * j;
        const float sa = s_scale[cr],     sha = s_shift[cr];
        const float sb = s_scale[cr + 1], shb = s_shift[cr + 1];
        float4 oa, ob;
        oa.x = fmaxf(fmaf(sa, va[0], sha), 0.f);
        oa.y = fmaxf(fmaf(sa, va[1], sha), 0.f);
        oa.z = fmaxf(fmaf(sa, va[2], sha), 0.f);
        oa.w = fmaxf(fmaf(sa, va[3], sha), 0.f);
        ob.x = fmaxf(fmaf(sb, vb[0], shb), 0.f);
        ob.y = fmaxf(fmaf(sb, vb[1], shb), 0.f);
        ob.z = fmaxf(fmaf(sb, vb[2], shb), 0.f);
        ob.w = fmaxf(fmaf(sb, vb[3], shb), 0.f);
        s_vals[cr * 128 + slot]       = oa;
        s_vals[(cr + 1) * 128 + slot] = ob;
    }
    __syncthreads();

    // ---- epilogue 2: partial conv1x1 over this half's 32 channels ----------
    const int c2b = 4 * cg;
    unsigned long long p01[4], p23[4];
#pragma unroll
    for (int c = 0; c < 4; c++) { p01[c] = 0ull; p23[c] = 0ull; }
#pragma unroll
    for (int j = 0; j < 32; j++) {
        float4 v = s_vals[j * 128 + slot];
        unsigned long long i01 = pk2(v.x, v.y);
        unsigned long long i23 = pk2(v.z, v.w);
#pragma unroll
        for (int c = 0; c < 4; c++) {
            unsigned long long w = s_w2[c2b + c][j];
            FMA2(p01[c], i01, w);
            FMA2(p23[c], i23, w);
        }
    }

    const int oy = y0t + yg;
    const int ox = x0t + 4 * xg;
    float* pp = g_p + (((size_t)(half * B_ + b) * 8 + c2b) << 16) + (oy << 8) + ox;
#pragma unroll
    for (int c = 0; c < 4; c++) {
        float f0, f1, f2, f3;
        upk2(p01[c], f0, f1);
        upk2(p23[c], f2, f3);
        *(float4*)(pp + ((size_t)c << 16)) = make_float4(f0, f1, f2, f3);
    }
}

// ---------------- sum 2 half-partials + BN2 + threshold + row-sum -----------
__global__ __launch_bounds__(256) void k_sum2(
    const float* __restrict__ gamma2, const float* __restrict__ beta2,
    const float* __restrict__ mean2, const float* __restrict__ var2)
{
    __shared__ float s_scale[8], s_shift[8];
    __shared__ float s_xf[8][4][264];   // data at idx 4..259; halo 2,3,260,261
    const int tid = threadIdx.x;
    const int b  = blockIdx.x >> 6;
    const int y0 = (blockIdx.x & 63) * 4;
    const int r = tid >> 6;
    const int col0 = (tid & 63) * 4;

    if (tid < 8) {
        float a = gamma2[tid] * rsqrtf(var2[tid] + 1e-5f);
        s_scale[tid] = a;
        s_shift[tid] = beta2[tid] - a * mean2[tid];
    }
    if (tid < 128) {
        int co = tid >> 4, rr = (tid >> 2) & 3, which = tid & 3;
        const int idxs[4] = {2, 3, 260, 261};
        s_xf[co][rr][idxs[which]] = 0.f;
    }
    __syncthreads();

    const size_t rowoff = ((size_t)(y0 + r) << 8) + col0;
#pragma unroll
    for (int co = 0; co < 8; co++) {
        float4 p0 = *(const float4*)(g_p + (((size_t)(0 * B_ + b) * 8 + co) << 16) + rowoff);
        float4 p1 = *(const float4*)(g_p + (((size_t)(1 * B_ + b) * 8 + co) << 16) + rowoff);
        float sx = p0.x + p1.x;
        float sy = p0.y + p1.y;
        float sz = p0.z + p1.z;
        float sw = p0.w + p1.w;
        const float sc = s_scale[co], sh = s_shift[co];
        float o0 = fmaf(sc, sx, sh), o1 = fmaf(sc, sy, sh);
        float o2 = fmaf(sc, sz, sh), o3 = fmaf(sc, sw, sh);
        float4 xf;
        xf.x = (o0 > 1.0f) ? o0 : 0.f;
        xf.y = (o1 > 1.0f) ? o1 : 0.f;
        xf.z = (o2 > 1.0f) ? o2 : 0.f;
        xf.w = (o3 > 1.0f) ? o3 : 0.f;
        *(float4*)(g_xf + (((size_t)b * COUT + co) << 16) + rowoff) = xf;
        *(float4*)&s_xf[co][r][col0 + 4] = xf;
    }
    __syncthreads();

#pragma unroll
    for (int co = 0; co < 8; co++) {
        const float* f = &s_xf[co][r][col0 + 2];
        float4 s;
        s.x = f[0] + f[1] + f[2] + f[3] + f[4];
        s.y = f[1] + f[2] + f[3] + f[4] + f[5];
        s.z = f[2] + f[3] + f[4] + f[5] + f[6];
        s.w = f[3] + f[4] + f[5] + f[6] + f[7];
        *(float4*)(g_rs + (((size_t)b * COUT + co) << 16) + rowoff) = s;
    }
}

// ---------------- fused ws + rowmax + NMS + per-segment top-8 ---------------
__global__ __launch_bounds__(256) void k_nms() {
    __shared__ __align__(16) float s_rs[24][256];   // aliased by s_rm after use
    __shared__ __align__(16) float s_ws[20][260];   // data cols 2..257; halo -1
    float (*s_rm)[256] = (float (*)[256])&s_rs[0][0];
    unsigned long long* s_keys = (unsigned long long*)&s_ws[0][0];

    const int bid = blockIdx.x;
    const int pl = bid >> 4;
    const int seg = bid & 15;
    const int y0 = seg * 16;
    const int x = threadIdx.x;
    const float* rs = g_rs + ((size_t)pl << 16);

#pragma unroll
    for (int i = 0; i < 24; i++) {
        int row = y0 - 4 + i;
        s_rs[i][x] = (row >= 0 && row < 256) ? rs[(row << 8) + x] : 0.f;
    }
    if (x < 80) {
        int rr = x >> 2, which = x & 3;
        const int idxs[4] = {0, 1, 258, 259};
        s_ws[rr][idxs[which]] = -1.f;
    }
    __syncthreads();

#pragma unroll
    for (int i = 0; i < 20; i++) {
        int y = y0 - 2 + i;
        float w;
        if (y >= 0 && y < 256)
            w = s_rs[i][x] + s_rs[i + 1][x] + s_rs[i + 2][x]
              + s_rs[i + 3][x] + s_rs[i + 4][x];
        else
            w = -1.f;
        s_ws[i][x + 2] = w;
    }
    __syncthreads();

#pragma unroll
    for (int i = 0; i < 20; i++) {
        const float* wr = &s_ws[i][x];
        s_rm[i][x] = fmaxf(fmaxf(fmaxf(wr[0], wr[1]), fmaxf(wr[2], wr[3])), wr[4]);
    }
    __syncthreads();

    unsigned long long k[8];
#pragma unroll
    for (int j = 0; j < 8; j++) k[j] = 0ull;

#pragma unroll
    for (int i = 0; i < 16; i++) {
        float m = fmaxf(fmaxf(fmaxf(s_rm[i][x], s_rm[i + 1][x]),
                              fmaxf(s_rm[i + 2][x], s_rm[i + 3][x])),
                        s_rm[i + 4][x]);
        float v = s_ws[i + 2][x + 2];
        if (v == m) {
            unsigned pos = (unsigned)(((y0 + i) << 8) + x);
            unsigned long long key =
                ((unsigned long long)__float_as_uint(v) << 32) | (unsigned)(~pos);
            if (key > k[7]) {
                int p = 7;
#pragma unroll
                for (int q = 7; q > 0; q--) {
                    if (key > k[q - 1]) { k[q] = k[q - 1]; p = q - 1; }
                }
                k[p] = key;
            }
        }
    }
    __syncthreads();

#pragma unroll
    for (int j = 0; j < 8; j++) s_keys[x * 8 + j] = k[j];
    __syncthreads();

    for (int off = 128; off > 0; off >>= 1) {
        if (x < off) {
            unsigned long long* a = &s_keys[x * 8];
            unsigned long long* b = &s_keys[(x + off) * 8];
            unsigned long long out[8];
            int i = 0, j = 0;
#pragma unroll
            for (int t = 0; t < 8; t++)
                out[t] = (a[i] >= b[j]) ? a[i++] : b[j++];
#pragma unroll
            for (int t = 0; t < 8; t++) a[t] = out[t];
        }
        __syncthreads();
    }
    if (x < 8) g_seg[bid * 8 + x] = s_keys[x];
}

// ---------------- top-k stage 2: parallel merge + spread gather -------------
__global__ __launch_bounds__(224) void k_topk2(float* __restrict__ out) {
    __shared__ unsigned long long s[NSEG * 8];
    const int bc = blockIdx.x;
    const int tid = threadIdx.x;

    if (tid < NSEG * 8) s[tid] = g_seg[bc * (NSEG * 8) + tid];
    __syncthreads();

    for (int off = NSEG / 2; off > 0; off >>= 1) {
        if (tid < off) {
            unsigned long long* a = &s[tid * 8];
            unsigned long long* b = &s[(tid + off) * 8];
            unsigned long long m[8];
            int i = 0, j = 0;
#pragma unroll
            for (int t = 0; t < 8; t++)
                m[t] = (a[i] >= b[j]) ? a[i++] : b[j++];
#pragma unroll
            for (int t = 0; t < 8; t++) a[t] = m[t];
        }
        __syncthreads();
    }

    if (tid < 200) {
        const int slotk = tid / 25;
        const int e = tid - slotk * 25;
        unsigned pos = ~(unsigned)(s[slotk] & 0xFFFFFFFFull);
        int h = pos >> 8, w = pos & 255;
        int yy = h + e / 5 - 2;
        int xx = w + e % 5 - 2;
        float v = 0.f;
        if (yy >= 0 && yy < 256 && xx >= 0 && xx < 256)
            v = g_xf[((size_t)bc << 16) + (yy << 8) + xx];
        out[(bc * 8 + slotk) * 25 + e] = v;
    }
    if (tid < 32) {
        const int slotk = tid >> 2;
        const int c = tid & 3;
        unsigned pos = ~(unsigned)(s[slotk] & 0xFFFFFFFFull);
        int h = pos >> 8, w = pos & 255;
        int val;
        if (c == 0)      val = min(max(w - 2, 0), 255);
        else if (c == 1) val = min(max(h - 2, 0), 255);
        else if (c == 2) val = min(max(w + 2, 0), 255);
        else             val = min(max(h + 2, 0), 255);
        out[B_ * COUT * NUM_ * 25 + (bc * 8 + slotk) * 4 + c] = (float)val;
    }
}

// ---------------- launch ------------------------------------------------------
extern "C" void kernel_launch(void* const* d_in, const int* in_sizes, int n_in,
                              void* d_out, int out_size) {
    const float* x      = (const float*)d_in[0];
    const float* w1     = (const float*)d_in[1];
    const float* b1     = (const float*)d_in[2];
    const float* gamma1 = (const float*)d_in[3];
    const float* beta1  = (const float*)d_in[4];
    const float* mean1  = (const float*)d_in[5];
    const float* var1   = (const float*)d_in[6];
    const float* w2     = (const float*)d_in[7];
    const float* gamma2 = (const float*)d_in[8];
    const float* beta2  = (const float*)d_in[9];
    const float* mean2  = (const float*)d_in[10];
    const float* var2   = (const float*)d_in[11];
    float* out = (float*)d_out;

    cudaFuncSetAttribute(k_conv1, cudaFuncAttributeMaxDynamicSharedMemorySize,
                         C1_SMEM_TOTAL);

    dim3 cg(2, 64, B_ * 2);
    k_conv1<<<cg, 256, C1_SMEM_TOTAL>>>(x, w1, b1, gamma1, beta1, mean1, var1, w2);

    k_sum2<<<B_ * 64, 256>>>(gamma2, beta2, mean2, var2);

    k_nms<<<B_ * COUT * NSEG, 256>>>();
    k_topk2<<<B_ * COUT, 224>>>(out);
}

// round 12
// speedup vs baseline: 1.2273x; 1.0307x over previous
#include <cuda_runtime.h>
#include <cstdint>

#define B_   8
#define CIN  64
#define COUT 8
#define H1   128
#define W1   128
#define H2   256
#define W2   256
#define PLANE (H2*W2)   /* 65536 */
#define NUM_ 8
#define NSEG 16

// ---------------- scratch (device globals; no allocation allowed) ----------
__device__ float g_p  [(size_t)2*B_*COUT*PLANE]; // conv2 partials per half
__device__ float g_xf [(size_t)B_*COUT*PLANE];   // conv2+BN, thresholded
__device__ float g_rs [(size_t)B_*COUT*PLANE];   // row sums
__device__ unsigned long long g_seg[B_*COUT*NSEG*8]; // per-segment top-8 keys

// ---------------- packed f32x2 helpers --------------------------------------
__device__ __forceinline__ unsigned long long pk2(float lo, float hi) {
    unsigned long long r;
    asm("mov.b64 %0, {%1, %2};" : "=l"(r) : "f"(lo), "f"(hi));
    return r;
}
__device__ __forceinline__ void upk2(unsigned long long v, float& lo, float& hi) {
    asm("mov.b64 {%0, %1}, %2;" : "=f"(lo), "=f"(hi) : "l"(v));
}
#define FMA2(d, a, b) asm("fma.rn.f32x2 %0, %1, %2, %0;" : "+l"(d) : "l"(a), "l"(b))

// dynamic smem layout for conv1
#define C1_W_BYTES    (CIN * 9 * 16 * 8)            /* 73728 */
#define C1_IN_BYTES   (2 * 2 * 6 * 136 * 4)         /* 13056 */
#define C1_W2_BYTES   (8 * 32 * 8)                  /* 2048  */
#define C1_SS_BYTES   (2 * 32 * 4)                  /* 256   */
#define C1_SMEM_TOTAL (C1_W_BYTES + C1_IN_BYTES + C1_W2_BYTES + C1_SS_BYTES)

// ============================================================================
// conv1: fused bilinear-2x-upsample + conv3x3(64->64) + bias + BN + ReLU
//        + per-half partial of conv1x1 (writes g_p, never materializes c1)
// grid (2, 64, B*2): tile 128(w) x 4(h), 32-co half per block.
// block 256 = 32 xg * 4 yg * 2 cg; thread: 4 px * 16 co (8 pairs, FFMA2).
// 2 input channels per barrier round (32 rounds instead of 64).
// ============================================================================
__global__ __launch_bounds__(256, 2) void k_conv1(
    const float* __restrict__ x,
    const float* __restrict__ w1, const float* __restrict__ b1,
    const float* __restrict__ gamma1, const float* __restrict__ beta1,
    const float* __restrict__ mean1, const float* __restrict__ var1,
    const float* __restrict__ w2)
{
    extern __shared__ __align__(16) unsigned char dsm[];
    unsigned long long (*s_w)[9][16] =
        (unsigned long long (*)[9][16])(dsm);                    // [ci][tap][pair]
    float (*s_in)[2][6][136] =
        (float (*)[2][6][136])(dsm + C1_W_BYTES);                // [buf][sub][r][c]
    unsigned long long (*s_w2)[32] =
        (unsigned long long (*)[32])(dsm + C1_W_BYTES + C1_IN_BYTES);
    float* s_scale = (float*)(dsm + C1_W_BYTES + C1_IN_BYTES + C1_W2_BYTES);
    float* s_shift = s_scale + 32;

    const int tid = threadIdx.x;
    const int xg = tid & 31;
    const int yg = (tid >> 5) & 3;
    const int cg = tid >> 7;               // 0/1: which 16-co group of the 32
    const int bz  = blockIdx.z;
    const int b    = bz >> 1;
    const int half = bz & 1;
    const int co0 = half * 32;
    const int x0t = blockIdx.x * 128;
    const int y0t = blockIdx.y * 4;

    const float* xb = x + (size_t)b * CIN * (H1 * W1);

    for (int i = tid; i < CIN * 9 * 16; i += 256) {
        int cp = i & 15; int rest = i >> 4;
        int p = rest % 9; int ci = rest / 9;
        int coA = co0 + 2 * cp;
        float wa = w1[((size_t)coA       * CIN + ci) * 9 + p];
        float wb = w1[((size_t)(coA + 1) * CIN + ci) * 9 + p];
        s_w[ci][p][cp] = pk2(wa, wb);
    }
    if (tid < 32) {
        int co = co0 + tid;
        float a = gamma1[co] * rsqrtf(var1[co] + 1e-5f);
        s_scale[tid] = a;
        s_shift[tid] = fmaf(a, b1[co] - mean1[co], beta1[co]);
    }
    {   // s_w2: exactly 256 entries (8 co2 x 32 ci-of-half)
        int co2 = tid >> 5, j = tid & 31;
        float w = w2[co2 * 64 + co0 + j];
        s_w2[co2][j] = pk2(w, w);
    }

    const bool runA = tid < 198;
    const int ur  = tid / 33;
    const int c0r = (tid - ur * 33) * 4;
    const int gy  = y0t + ur - 1;
    const int gx0 = x0t + c0r - 1;
    const int sy  = (gy - 1) >> 1;
    const int ro0 = min(max(sy, 0), H1 - 1) * W1;
    const int ro1 = min(max(sy + 1, 0), H1 - 1) * W1;
    const float wyv = (gy & 1) ? 0.25f : 0.75f;
    const int S   = (gx0 - 1) >> 1;
    const int cS0 = min(max(S, 0), W1 - 1);
    const int cS1 = min(max(S + 1, 0), W1 - 1);
    const int cS2 = min(max(S + 2, 0), W1 - 1);
    const bool rowOK = (gy >= 0) && (gy < H2);
    bool mok[4];
#pragma unroll
    for (int j = 0; j < 4; j++) {
        int gx = gx0 + j;
        mok[j] = rowOK && (gx >= 0) && (gx < W2);
    }

#define BILIN(buf, sub, p0a, p0b, p0c, p1a, p1b, p1c) do {                    \
        float t0 = p0a + 0.25f * (p0b - p0a);                                 \
        float t1 = p0a + 0.75f * (p0b - p0a);                                 \
        float t2 = p0b + 0.25f * (p0c - p0b);                                 \
        float t3 = p0b + 0.75f * (p0c - p0b);                                 \
        float u0 = p1a + 0.25f * (p1b - p1a);                                 \
        float u1 = p1a + 0.75f * (p1b - p1a);                                 \
        float u2 = p1b + 0.25f * (p1c - p1b);                                 \
        float u3 = p1b + 0.75f * (p1c - p1b);                                 \
        float4 o;                                                             \
        o.x = mok[0] ? (t0 + wyv * (u0 - t0)) : 0.f;                          \
        o.y = mok[1] ? (t1 + wyv * (u1 - t1)) : 0.f;                          \
        o.z = mok[2] ? (t2 + wyv * (u2 - t2)) : 0.f;                          \
        o.w = mok[3] ? (t3 + wyv * (u3 - t3)) : 0.f;                          \
        *(float4*)&s_in[buf][sub][ur][c0r] = o;                               \
    } while (0)

#define LOAD6(ci, pa) do {                                                    \
        const float* xp_ = xb + ((size_t)(ci) << 14);                         \
        (pa)[0] = xp_[ro0 + cS0]; (pa)[1] = xp_[ro0 + cS1];                   \
        (pa)[2] = xp_[ro0 + cS2];                                             \
        (pa)[3] = xp_[ro1 + cS0]; (pa)[4] = xp_[ro1 + cS1];                   \
        (pa)[5] = xp_[ro1 + cS2];                                             \
    } while (0)

    if (runA) {
        float pa[6], pb[6];
        LOAD6(0, pa);
        LOAD6(1, pb);
        BILIN(0, 0, pa[0], pa[1], pa[2], pa[3], pa[4], pa[5]);
        BILIN(0, 1, pb[0], pb[1], pb[2], pb[3], pb[4], pb[5]);
    }
    __syncthreads();

    unsigned long long acc[4][8];
#pragma unroll
    for (int q = 0; q < 4; q++)
#pragma unroll
        for (int j = 0; j < 8; j++) acc[q][j] = 0ull;

    for (int cc = 0; cc < CIN; cc += 2) {
        const int cur = (cc >> 1) & 1;

        float pa[6], pb[6];
        if (runA && cc + 2 < CIN) {
            LOAD6(cc + 2, pa);
            LOAD6(cc + 3, pb);
        }

#pragma unroll
        for (int sub = 0; sub < 2; sub++) {
            const int ci = cc + sub;
#pragma unroll
            for (int kr = 0; kr < 3; kr++) {
                const float* row = &s_in[cur][sub][yg + kr][4 * xg];
                float4 F = *(const float4*)row;
                float2 G = *(const float2*)(row + 4);
                unsigned long long Q[6];
                Q[0] = pk2(F.x, F.x);
                Q[1] = pk2(F.y, F.y);
                Q[2] = pk2(F.z, F.z);
                Q[3] = pk2(F.w, F.w);
                Q[4] = pk2(G.x, G.x);
                Q[5] = pk2(G.y, G.y);
#pragma unroll
                for (int kc = 0; kc < 3; kc++) {
                    const ulonglong2* wrow =
                        (const ulonglong2*)&s_w[ci][kr * 3 + kc][cg * 8];
                    ulonglong2 wA = wrow[0];
                    ulonglong2 wB = wrow[1];
                    ulonglong2 wC = wrow[2];
                    ulonglong2 wD = wrow[3];
#pragma unroll
                    for (int q = 0; q < 4; q++) {
                        unsigned long long iv = Q[kc + q];
                        FMA2(acc[q][0], iv, wA.x);
                        FMA2(acc[q][1], iv, wA.y);
                        FMA2(acc[q][2], iv, wB.x);
                        FMA2(acc[q][3], iv, wB.y);
                        FMA2(acc[q][4], iv, wC.x);
                        FMA2(acc[q][5], iv, wC.y);
                        FMA2(acc[q][6], iv, wD.x);
                        FMA2(acc[q][7], iv, wD.y);
                    }
                }
            }
        }

        if (runA && cc + 2 < CIN) {
            BILIN(cur ^ 1, 0, pa[0], pa[1], pa[2], pa[3], pa[4], pa[5]);
            BILIN(cur ^ 1, 1, pb[0], pb[1], pb[2], pb[3], pb[4], pb[5]);
        }
        __syncthreads();
    }
#undef BILIN
#undef LOAD6

    // ---- epilogue 1: BN + ReLU, stage vals in smem (overlay s_w, now dead)
    float4* s_vals = (float4*)&s_w[0][0][0];   // [32 ci][128 slots] float4 (64KB)
    const int slot = tid & 127;
#pragma unroll
    for (int j = 0; j < 8; j++) {
        float va[4], vb[4];
#pragma unroll
        for (int q = 0; q < 4; q++) upk2(acc[q][j], va[q], vb[q]);
        const int cr = 16 * cg + 2 * j;
        const float sa = s_scale[cr],     sha = s_shift[cr];
        const float sb = s_scale[cr + 1], shb = s_shift[cr + 1];
        float4 oa, ob;
        oa.x = fmaxf(fmaf(sa, va[0], sha), 0.f);
        oa.y = fmaxf(fmaf(sa, va[1], sha), 0.f);
        oa.z = fmaxf(fmaf(sa, va[2], sha), 0.f);
        oa.w = fmaxf(fmaf(sa, va[3], sha), 0.f);
        ob.x = fmaxf(fmaf(sb, vb[0], shb), 0.f);
        ob.y = fmaxf(fmaf(sb, vb[1], shb), 0.f);
        ob.z = fmaxf(fmaf(sb, vb[2], shb), 0.f);
        ob.w = fmaxf(fmaf(sb, vb[3], shb), 0.f);
        s_vals[cr * 128 + slot]       = oa;
        s_vals[(cr + 1) * 128 + slot] = ob;
    }
    __syncthreads();

    // ---- epilogue 2: partial conv1x1 over this half's 32 channels ----------
    const int c2b = 4 * cg;
    unsigned long long p01[4], p23[4];
#pragma unroll
    for (int c = 0; c < 4; c++) { p01[c] = 0ull; p23[c] = 0ull; }
#pragma unroll
    for (int j = 0; j < 32; j++) {
        float4 v = s_vals[j * 128 + slot];
        unsigned long long i01 = pk2(v.x, v.y);
        unsigned long long i23 = pk2(v.z, v.w);
#pragma unroll
        for (int c = 0; c < 4; c++) {
            unsigned long long w = s_w2[c2b + c][j];
            FMA2(p01[c], i01, w);
            FMA2(p23[c], i23, w);
        }
    }

    const int oy = y0t + yg;
    const int ox = x0t + 4 * xg;
    float* pp = g_p + (((size_t)(half * B_ + b) * 8 + c2b) << 16) + (oy << 8) + ox;
#pragma unroll
    for (int c = 0; c < 4; c++) {
        float f0, f1, f2, f3;
        upk2(p01[c], f0, f1);
        upk2(p23[c], f2, f3);
        *(float4*)(pp + ((size_t)c << 16)) = make_float4(f0, f1, f2, f3);
    }
}

// ---------------- sum 2 half-partials + BN2 + threshold + row-sum -----------
__global__ __launch_bounds__(256) void k_sum2(
    const float* __restrict__ gamma2, const float* __restrict__ beta2,
    const float* __restrict__ mean2, const float* __restrict__ var2)
{
    __shared__ float s_scale[8], s_shift[8];
    __shared__ float s_xf[8][4][264];   // data at idx 4..259; halo 2,3,260,261
    const int tid = threadIdx.x;
    const int b  = blockIdx.x >> 6;
    const int y0 = (blockIdx.x & 63) * 4;
    const int r = tid >> 6;
    const int col0 = (tid & 63) * 4;

    if (tid < 8) {
        float a = gamma2[tid] * rsqrtf(var2[tid] + 1e-5f);
        s_scale[tid] = a;
        s_shift[tid] = beta2[tid] - a * mean2[tid];
    }
    if (tid < 128) {
        int co = tid >> 4, rr = (tid >> 2) & 3, which = tid & 3;
        const int idxs[4] = {2, 3, 260, 261};
        s_xf[co][rr][idxs[which]] = 0.f;
    }
    __syncthreads();

    const size_t rowoff = ((size_t)(y0 + r) << 8) + col0;
#pragma unroll
    for (int co = 0; co < 8; co++) {
        float4 p0 = *(const float4*)(g_p + (((size_t)(0 * B_ + b) * 8 + co) << 16) + rowoff);
        float4 p1 = *(const float4*)(g_p + (((size_t)(1 * B_ + b) * 8 + co) << 16) + rowoff);
        float sx = p0.x + p1.x;
        float sy = p0.y + p1.y;
        float sz = p0.z + p1.z;
        float sw = p0.w + p1.w;
        const float sc = s_scale[co], sh = s_shift[co];
        float o0 = fmaf(sc, sx, sh), o1 = fmaf(sc, sy, sh);
        float o2 = fmaf(sc, sz, sh), o3 = fmaf(sc, sw, sh);
        float4 xf;
        xf.x = (o0 > 1.0f) ? o0 : 0.f;
        xf.y = (o1 > 1.0f) ? o1 : 0.f;
        xf.z = (o2 > 1.0f) ? o2 : 0.f;
        xf.w = (o3 > 1.0f) ? o3 : 0.f;
        *(float4*)(g_xf + (((size_t)b * COUT + co) << 16) + rowoff) = xf;
        *(float4*)&s_xf[co][r][col0 + 4] = xf;
    }
    __syncthreads();

#pragma unroll
    for (int co = 0; co < 8; co++) {
        const float* f = &s_xf[co][r][col0 + 2];
        float4 s;
        s.x = f[0] + f[1] + f[2] + f[3] + f[4];
        s.y = f[1] + f[2] + f[3] + f[4] + f[5];
        s.z = f[2] + f[3] + f[4] + f[5] + f[6];
        s.w = f[3] + f[4] + f[5] + f[6] + f[7];
        *(float4*)(g_rs + (((size_t)b * COUT + co) << 16) + rowoff) = s;
    }
}

// ---------------- fused ws + rowmax + NMS + per-segment top-8 ---------------
__global__ __launch_bounds__(256) void k_nms() {
    __shared__ __align__(16) float s_rs[24][256];   // aliased by s_rm after use
    __shared__ __align__(16) float s_ws[20][260];   // data cols 2..257; halo -1
    float (*s_rm)[256] = (float (*)[256])&s_rs[0][0];
    unsigned long long* s_keys = (unsigned long long*)&s_ws[0][0];

    const int bid = blockIdx.x;
    const int pl = bid >> 4;
    const int seg = bid & 15;
    const int y0 = seg * 16;
    const int x = threadIdx.x;
    const float* rs = g_rs + ((size_t)pl << 16);

#pragma unroll
    for (int i = 0; i < 24; i++) {
        int row = y0 - 4 + i;
        s_rs[i][x] = (row >= 0 && row < 256) ? rs[(row << 8) + x] : 0.f;
    }
    if (x < 80) {
        int rr = x >> 2, which = x & 3;
        const int idxs[4] = {0, 1, 258, 259};
        s_ws[rr][idxs[which]] = -1.f;
    }
    __syncthreads();

#pragma unroll
    for (int i = 0; i < 20; i++) {
        int y = y0 - 2 + i;
        float w;
        if (y >= 0 && y < 256)
            w = s_rs[i][x] + s_rs[i + 1][x] + s_rs[i + 2][x]
              + s_rs[i + 3][x] + s_rs[i + 4][x];
        else
            w = -1.f;
        s_ws[i][x + 2] = w;
    }
    __syncthreads();

#pragma unroll
    for (int i = 0; i < 20; i++) {
        const float* wr = &s_ws[i][x];
        s_rm[i][x] = fmaxf(fmaxf(fmaxf(wr[0], wr[1]), fmaxf(wr[2], wr[3])), wr[4]);
    }
    __syncthreads();

    unsigned long long k[8];
#pragma unroll
    for (int j = 0; j < 8; j++) k[j] = 0ull;

#pragma unroll
    for (int i = 0; i < 16; i++) {
        float m = fmaxf(fmaxf(fmaxf(s_rm[i][x], s_rm[i + 1][x]),
                              fmaxf(s_rm[i + 2][x], s_rm[i + 3][x])),
                        s_rm[i + 4][x]);
        float v = s_ws[i + 2][x + 2];
        if (v == m) {
            unsigned pos = (unsigned)(((y0 + i) << 8) + x);
            unsigned long long key =
                ((unsigned long long)__float_as_uint(v) << 32) | (unsigned)(~pos);
            if (key > k[7]) {
                int p = 7;
#pragma unroll
                for (int q = 7; q > 0; q--) {
                    if (key > k[q - 1]) { k[q] = k[q - 1]; p = q - 1; }
                }
                k[p] = key;
            }
        }
    }
    __syncthreads();

#pragma unroll
    for (int j = 0; j < 8; j++) s_keys[x * 8 + j] = k[j];
    __syncthreads();

    for (int off = 128; off > 0; off >>= 1) {
        if (x < off) {
            unsigned long long* a = &s_keys[x * 8];
            unsigned long long* b = &s_keys[(x + off) * 8];
            unsigned long long out[8];
            int i = 0, j = 0;
#pragma unroll
            for (int t = 0; t < 8; t++)
                out[t] = (a[i] >= b[j]) ? a[i++] : b[j++];
#pragma unroll
            for (int t = 0; t < 8; t++) a[t] = out[t];
        }
        __syncthreads();
    }
    if (x < 8) g_seg[bid * 8 + x] = s_keys[x];
}

// ---------------- top-k stage 2: parallel merge + spread gather -------------
__global__ __launch_bounds__(224) void k_topk2(float* __restrict__ out) {
    __shared__ unsigned long long s[NSEG * 8];
    const int bc = blockIdx.x;
    const int tid = threadIdx.x;

    if (tid < NSEG * 8) s[tid] = g_seg[bc * (NSEG * 8) + tid];
    __syncthreads();

    for (int off = NSEG / 2; off > 0; off >>= 1) {
        if (tid < off) {
            unsigned long long* a = &s[tid * 8];
            unsigned long long* b = &s[(tid + off) * 8];
            unsigned long long m[8];
            int i = 0, j = 0;
#pragma unroll
            for (int t = 0; t < 8; t++)
                m[t] = (a[i] >= b[j]) ? a[i++] : b[j++];
#pragma unroll
            for (int t = 0; t < 8; t++) a[t] = m[t];
        }
        __syncthreads();
    }

    if (tid < 200) {
        const int slotk = tid / 25;
        const int e = tid - slotk * 25;
        unsigned pos = ~(unsigned)(s[slotk] & 0xFFFFFFFFull);
        int h = pos >> 8, w = pos & 255;
        int yy = h + e / 5 - 2;
        int xx = w + e % 5 - 2;
        float v = 0.f;
        if (yy >= 0 && yy < 256 && xx >= 0 && xx < 256)
            v = g_xf[((size_t)bc << 16) + (yy << 8) + xx];
        out[(bc * 8 + slotk) * 25 + e] = v;
    }
    if (tid < 32) {
        const int slotk = tid >> 2;
        const int c = tid & 3;
        unsigned pos = ~(unsigned)(s[slotk] & 0xFFFFFFFFull);
        int h = pos >> 8, w = pos & 255;
        int val;
        if (c == 0)      val = min(max(w - 2, 0), 255);
        else if (c == 1) val = min(max(h - 2, 0), 255);
        else if (c == 2) val = min(max(w + 2, 0), 255);
        else             val = min(max(h + 2, 0), 255);
        out[B_ * COUT * NUM_ * 25 + (bc * 8 + slotk) * 4 + c] = (float)val;
    }
}

// ---------------- launch ------------------------------------------------------
extern "C" void kernel_launch(void* const* d_in, const int* in_sizes, int n_in,
                              void* d_out, int out_size) {
    const float* x      = (const float*)d_in[0];
    const float* w1     = (const float*)d_in[1];
    const float* b1     = (const float*)d_in[2];
    const float* gamma1 = (const float*)d_in[3];
    const float* beta1  = (const float*)d_in[4];
    const float* mean1  = (const float*)d_in[5];
    const float* var1   = (const float*)d_in[6];
    const float* w2     = (const float*)d_in[7];
    const float* gamma2 = (const float*)d_in[8];
    const float* beta2  = (const float*)d_in[9];
    const float* mean2  = (const float*)d_in[10];
    const float* var2   = (const float*)d_in[11];
    float* out = (float*)d_out;

    cudaFuncSetAttribute(k_conv1, cudaFuncAttributeMaxDynamicSharedMemorySize,
                         C1_SMEM_TOTAL);

    dim3 cg(2, 64, B_ * 2);
    k_conv1<<<cg, 256, C1_SMEM_TOTAL>>>(x, w1, b1, gamma1, beta1, mean1, var1, w2);

    k_sum2<<<B_ * 64, 256>>>(gamma2, beta2, mean2, var2);

    k_nms<<<B_ * COUT * NSEG, 256>>>();
    k_topk2<<<B_ * COUT, 224>>>(out);
}